// round 3
// baseline (speedup 1.0000x reference)
#include <cuda_runtime.h>
#include <math_constants.h>

// Problem constants
#define B_   2
#define NQ_  2048
#define NK_  2048
#define R_   512
#define H_   8
#define D_   64
#define HD_  512
#define M_   (B_ * NQ_)   // 4096 rows for all projection GEMMs

// ---------------------------------------------------------------------------
// Scratch (device globals; no allocations allowed)
// ---------------------------------------------------------------------------
__device__ float g_qr[M_ * HD_];
__device__ float g_qi[M_ * HD_];
__device__ float g_kr[M_ * HD_];
__device__ float g_ki[M_ * HD_];
__device__ float g_vr[M_ * HD_];
__device__ float g_vi[M_ * HD_];
__device__ float g_or[M_ * HD_];
__device__ float g_oi[M_ * HD_];

// ---------------------------------------------------------------------------
// Fused complex GEMM (NT):  Y = (Xr + i Xi) @ (Wr + i Wi)^T
//   Yr = Xr Wr^T - Xi Wi^T ;  Yi = Xr Wi^T + Xi Wr^T
// X: (M, K) row-major; W: (N, K) row-major (weights stored (out, in)).
// Output element stride `es` (1 = planar arrays, 2 = interleaved re/im).
// Tiles: 64x64x16, 256 threads, 4x4 register blocking, both outputs fused.
// ---------------------------------------------------------------------------
__global__ __launch_bounds__(256) void cgemm_nt(
    const float* __restrict__ Xr, const float* __restrict__ Xi,
    const float* __restrict__ Wr, const float* __restrict__ Wi,
    float* __restrict__ Yr, float* __restrict__ Yi,
    int N, int K, int es)
{
    __shared__ float Asr[16][64], Asi[16][64], Bsr[16][64], Bsi[16][64];

    const int tid = threadIdx.x;
    const int tx = tid & 15, ty = tid >> 4;
    const int m0 = blockIdx.y * 64, n0 = blockIdx.x * 64;
    const int lrow = tid >> 2;          // 0..63
    const int lk   = (tid & 3) * 4;     // 0,4,8,12

    float accr[4][4], acci[4][4];
#pragma unroll
    for (int i = 0; i < 4; i++)
#pragma unroll
        for (int j = 0; j < 4; j++) { accr[i][j] = 0.f; acci[i][j] = 0.f; }

    for (int k0 = 0; k0 < K; k0 += 16) {
        float4 xr = *(const float4*)(Xr + (size_t)(m0 + lrow) * K + k0 + lk);
        float4 xi = *(const float4*)(Xi + (size_t)(m0 + lrow) * K + k0 + lk);
        float4 wr = *(const float4*)(Wr + (size_t)(n0 + lrow) * K + k0 + lk);
        float4 wi = *(const float4*)(Wi + (size_t)(n0 + lrow) * K + k0 + lk);
        __syncthreads();
        Asr[lk + 0][lrow] = xr.x; Asr[lk + 1][lrow] = xr.y;
        Asr[lk + 2][lrow] = xr.z; Asr[lk + 3][lrow] = xr.w;
        Asi[lk + 0][lrow] = xi.x; Asi[lk + 1][lrow] = xi.y;
        Asi[lk + 2][lrow] = xi.z; Asi[lk + 3][lrow] = xi.w;
        Bsr[lk + 0][lrow] = wr.x; Bsr[lk + 1][lrow] = wr.y;
        Bsr[lk + 2][lrow] = wr.z; Bsr[lk + 3][lrow] = wr.w;
        Bsi[lk + 0][lrow] = wi.x; Bsi[lk + 1][lrow] = wi.y;
        Bsi[lk + 2][lrow] = wi.z; Bsi[lk + 3][lrow] = wi.w;
        __syncthreads();

#pragma unroll
        for (int k = 0; k < 16; k++) {
            float4 a_r = *(const float4*)&Asr[k][ty * 4];
            float4 a_i = *(const float4*)&Asi[k][ty * 4];
            float4 b_r = *(const float4*)&Bsr[k][tx * 4];
            float4 b_i = *(const float4*)&Bsi[k][tx * 4];
            float ar[4] = {a_r.x, a_r.y, a_r.z, a_r.w};
            float ai[4] = {a_i.x, a_i.y, a_i.z, a_i.w};
            float br[4] = {b_r.x, b_r.y, b_r.z, b_r.w};
            float bi[4] = {b_i.x, b_i.y, b_i.z, b_i.w};
#pragma unroll
            for (int i = 0; i < 4; i++) {
                float nai = -ai[i];
#pragma unroll
                for (int j = 0; j < 4; j++) {
                    accr[i][j] = fmaf(ar[i],  br[j], accr[i][j]);
                    accr[i][j] = fmaf(nai,    bi[j], accr[i][j]);
                    acci[i][j] = fmaf(ar[i],  bi[j], acci[i][j]);
                    acci[i][j] = fmaf(ai[i],  br[j], acci[i][j]);
                }
            }
        }
    }

#pragma unroll
    for (int i = 0; i < 4; i++)
#pragma unroll
        for (int j = 0; j < 4; j++) {
            size_t idx = ((size_t)(m0 + ty * 4 + i) * N + (n0 + tx * 4 + j)) * (size_t)es;
            Yr[idx] = accr[i][j];
            Yi[idx] = acci[i][j];
        }
}

// ---------------------------------------------------------------------------
// Fused complex-magnitude flash attention (fp32).
// Per block: one (b, h), one 64-row q tile. Loops over 32 k tiles of 64.
//   s_re = Qr.Kr + Qi.Ki ; s_im = Qi.Kr - Qr.Ki
//   mag = |s| * (1/8) ; online softmax over mag ; O(+re/+im) = P @ V
// Smem (dynamic, 96 KB): Qr,Qi,Kr,Ki (all [d][n] transposed), Vr,Vi ([n][d]).
// P tile reuses the Kr buffer after scores are consumed.
// ---------------------------------------------------------------------------
__global__ __launch_bounds__(256, 2) void cattn_kernel()
{
    extern __shared__ float sm[];
    float* sQr = sm;            // [64][64]  (d-major)
    float* sQi = sm + 4096;
    float* sKr = sm + 8192;     // [64][64]  (d-major); reused as P [m][n]
    float* sKi = sm + 12288;
    float* sVr = sm + 16384;    // [64][64]  (n-major)
    float* sVi = sm + 20480;
    float* sP  = sKr;

    const int tid = threadIdx.x;
    const int tx = tid & 15, ty = tid >> 4;
    const int q0 = blockIdx.x * 64;
    const int bh = blockIdx.y;
    const int b  = bh >> 3, h = bh & 7;
    const int col0 = h * D_;

    const int lrow = tid >> 2;          // 0..63
    const int lc   = (tid & 3) * 16;    // 0,16,32,48

    // --- Load Q tile (transposed into [d][m]) ---
    {
        const float* qr = g_qr + (size_t)(b * NQ_ + q0 + lrow) * HD_ + col0;
        const float* qi = g_qi + (size_t)(b * NQ_ + q0 + lrow) * HD_ + col0;
#pragma unroll
        for (int u = 0; u < 4; u++) {
            int d = lc + u * 4;
            float4 fr = *(const float4*)(qr + d);
            float4 fi = *(const float4*)(qi + d);
            sQr[(d + 0) * 64 + lrow] = fr.x; sQr[(d + 1) * 64 + lrow] = fr.y;
            sQr[(d + 2) * 64 + lrow] = fr.z; sQr[(d + 3) * 64 + lrow] = fr.w;
            sQi[(d + 0) * 64 + lrow] = fi.x; sQi[(d + 1) * 64 + lrow] = fi.y;
            sQi[(d + 2) * 64 + lrow] = fi.z; sQi[(d + 3) * 64 + lrow] = fi.w;
        }
    }

    float mi[4], li[4], o_r[4][4], o_i[4][4];
#pragma unroll
    for (int i = 0; i < 4; i++) {
        mi[i] = -CUDART_INF_F; li[i] = 0.f;
#pragma unroll
        for (int j = 0; j < 4; j++) { o_r[i][j] = 0.f; o_i[i][j] = 0.f; }
    }

    for (int nt = 0; nt < NK_ / 64; nt++) {
        const int n0 = nt * 64;
        const size_t rowbase = (size_t)(b * NK_ + n0 + lrow) * HD_ + col0;
        const float* kr = g_kr + rowbase;
        const float* ki = g_ki + rowbase;
        const float* vr = g_vr + rowbase;
        const float* vi = g_vi + rowbase;

        __syncthreads();   // previous iteration finished reading sP/sV
#pragma unroll
        for (int u = 0; u < 4; u++) {
            int d = lc + u * 4;
            float4 fr = *(const float4*)(kr + d);
            float4 fi = *(const float4*)(ki + d);
            sKr[(d + 0) * 64 + lrow] = fr.x; sKr[(d + 1) * 64 + lrow] = fr.y;
            sKr[(d + 2) * 64 + lrow] = fr.z; sKr[(d + 3) * 64 + lrow] = fr.w;
            sKi[(d + 0) * 64 + lrow] = fi.x; sKi[(d + 1) * 64 + lrow] = fi.y;
            sKi[(d + 2) * 64 + lrow] = fi.z; sKi[(d + 3) * 64 + lrow] = fi.w;
            *(float4*)&sVr[lrow * 64 + d] = *(const float4*)(vr + d);
            *(float4*)&sVi[lrow * 64 + d] = *(const float4*)(vi + d);
        }
        __syncthreads();

        // --- scores: 4x4 per thread ---
        float sre[4][4], simg[4][4];
#pragma unroll
        for (int i = 0; i < 4; i++)
#pragma unroll
            for (int j = 0; j < 4; j++) { sre[i][j] = 0.f; simg[i][j] = 0.f; }

#pragma unroll 8
        for (int d = 0; d < 64; d++) {
            float4 q_r = *(const float4*)&sQr[d * 64 + ty * 4];
            float4 q_i = *(const float4*)&sQi[d * 64 + ty * 4];
            float4 k_r = *(const float4*)&sKr[d * 64 + tx * 4];
            float4 k_i = *(const float4*)&sKi[d * 64 + tx * 4];
            float qr_[4] = {q_r.x, q_r.y, q_r.z, q_r.w};
            float qi_[4] = {q_i.x, q_i.y, q_i.z, q_i.w};
            float kr_[4] = {k_r.x, k_r.y, k_r.z, k_r.w};
            float ki_[4] = {k_i.x, k_i.y, k_i.z, k_i.w};
#pragma unroll
            for (int i = 0; i < 4; i++) {
                float nqr = -qr_[i];
#pragma unroll
                for (int j = 0; j < 4; j++) {
                    sre[i][j]  = fmaf(qr_[i],  kr_[j], sre[i][j]);
                    sre[i][j]  = fmaf(qi_[i],  ki_[j], sre[i][j]);
                    simg[i][j] = fmaf(qi_[i],  kr_[j], simg[i][j]);
                    simg[i][j] = fmaf(nqr,     ki_[j], simg[i][j]);
                }
            }
        }
        __syncthreads();   // done reading sKr/sKi; safe to overwrite with P

        // --- magnitude + online softmax (rows owned by 16-lane groups) ---
#pragma unroll
        for (int i = 0; i < 4; i++) {
            float p[4];
            float rmax = -CUDART_INF_F;
#pragma unroll
            for (int j = 0; j < 4; j++) {
                float s2 = fmaf(sre[i][j], sre[i][j], simg[i][j] * simg[i][j]) + 1e-30f;
                float mag = s2 * rsqrtf(s2) * 0.125f;
                p[j] = mag;
                rmax = fmaxf(rmax, mag);
            }
#pragma unroll
            for (int s = 8; s; s >>= 1)
                rmax = fmaxf(rmax, __shfl_xor_sync(0xffffffffu, rmax, s));
            float mnew  = fmaxf(mi[i], rmax);
            float alpha = __expf(mi[i] - mnew);
            float rsum = 0.f;
#pragma unroll
            for (int j = 0; j < 4; j++) { p[j] = __expf(p[j] - mnew); rsum += p[j]; }
#pragma unroll
            for (int s = 8; s; s >>= 1)
                rsum += __shfl_xor_sync(0xffffffffu, rsum, s);
            li[i] = li[i] * alpha + rsum;
            mi[i] = mnew;
#pragma unroll
            for (int j = 0; j < 4; j++) { o_r[i][j] *= alpha; o_i[i][j] *= alpha; }
            *(float4*)&sP[(ty * 4 + i) * 64 + tx * 4] = make_float4(p[0], p[1], p[2], p[3]);
        }
        __syncthreads();

        // --- O += P @ V ---
#pragma unroll 8
        for (int n = 0; n < 64; n++) {
            float4 v_r = *(const float4*)&sVr[n * 64 + tx * 4];
            float4 v_i = *(const float4*)&sVi[n * 64 + tx * 4];
#pragma unroll
            for (int i = 0; i < 4; i++) {
                float pv = sP[(ty * 4 + i) * 64 + n];
                o_r[i][0] = fmaf(pv, v_r.x, o_r[i][0]);
                o_r[i][1] = fmaf(pv, v_r.y, o_r[i][1]);
                o_r[i][2] = fmaf(pv, v_r.z, o_r[i][2]);
                o_r[i][3] = fmaf(pv, v_r.w, o_r[i][3]);
                o_i[i][0] = fmaf(pv, v_i.x, o_i[i][0]);
                o_i[i][1] = fmaf(pv, v_i.y, o_i[i][1]);
                o_i[i][2] = fmaf(pv, v_i.z, o_i[i][2]);
                o_i[i][3] = fmaf(pv, v_i.w, o_i[i][3]);
            }
        }
    }

    // --- epilogue: O / l, write merged-head layout (b, q, h*64+d) ---
#pragma unroll
    for (int i = 0; i < 4; i++) {
        float inv = 1.0f / li[i];
        size_t base = (size_t)(b * NQ_ + q0 + ty * 4 + i) * HD_ + col0 + tx * 4;
        *(float4*)&g_or[base] = make_float4(o_r[i][0] * inv, o_r[i][1] * inv,
                                            o_r[i][2] * inv, o_r[i][3] * inv);
        *(float4*)&g_oi[base] = make_float4(o_i[i][0] * inv, o_i[i][1] * inv,
                                            o_i[i][2] * inv, o_i[i][3] * inv);
    }
}

// Tiny wrapper kernels that read the device-global scratch directly would
// require templated pointers; instead we pass the globals' addresses from
// device-side launch? Not needed: referencing __device__ globals from host
// requires an address. We avoid cudaGetSymbolAddress by using a small
// device-side "address export" kernel-free trick: a __device__ pointer table
// initialized at compile time, read via a launch-time kernel is overkill.
// Simplest robust approach: wrapper kernels take no pointer args at all and
// use the globals directly -- cgemm needs to work on both globals and true
// inputs, so only the projection-output / attention paths use globals.

// GEMM variant writing to globals (Q/K/V projections): selects target by id.
__global__ __launch_bounds__(256) void cgemm_nt_proj(
    const float* __restrict__ Xr, const float* __restrict__ Xi,
    const float* __restrict__ Wr, const float* __restrict__ Wi,
    int which)   // 0 = Q, 1 = K, 2 = V
{
    float* Yr = (which == 0) ? g_qr : (which == 1) ? g_kr : g_vr;
    float* Yi = (which == 0) ? g_qi : (which == 1) ? g_ki : g_vi;

    __shared__ float Asr[16][64], Asi[16][64], Bsr[16][64], Bsi[16][64];
    const int tid = threadIdx.x;
    const int tx = tid & 15, ty = tid >> 4;
    const int m0 = blockIdx.y * 64, n0 = blockIdx.x * 64;
    const int lrow = tid >> 2;
    const int lk   = (tid & 3) * 4;
    const int K = R_, N = HD_;

    float accr[4][4], acci[4][4];
#pragma unroll
    for (int i = 0; i < 4; i++)
#pragma unroll
        for (int j = 0; j < 4; j++) { accr[i][j] = 0.f; acci[i][j] = 0.f; }

    for (int k0 = 0; k0 < K; k0 += 16) {
        float4 xr = *(const float4*)(Xr + (size_t)(m0 + lrow) * K + k0 + lk);
        float4 xi = *(const float4*)(Xi + (size_t)(m0 + lrow) * K + k0 + lk);
        float4 wr = *(const float4*)(Wr + (size_t)(n0 + lrow) * K + k0 + lk);
        float4 wi = *(const float4*)(Wi + (size_t)(n0 + lrow) * K + k0 + lk);
        __syncthreads();
        Asr[lk + 0][lrow] = xr.x; Asr[lk + 1][lrow] = xr.y;
        Asr[lk + 2][lrow] = xr.z; Asr[lk + 3][lrow] = xr.w;
        Asi[lk + 0][lrow] = xi.x; Asi[lk + 1][lrow] = xi.y;
        Asi[lk + 2][lrow] = xi.z; Asi[lk + 3][lrow] = xi.w;
        Bsr[lk + 0][lrow] = wr.x; Bsr[lk + 1][lrow] = wr.y;
        Bsr[lk + 2][lrow] = wr.z; Bsr[lk + 3][lrow] = wr.w;
        Bsi[lk + 0][lrow] = wi.x; Bsi[lk + 1][lrow] = wi.y;
        Bsi[lk + 2][lrow] = wi.z; Bsi[lk + 3][lrow] = wi.w;
        __syncthreads();

#pragma unroll
        for (int k = 0; k < 16; k++) {
            float4 a_r = *(const float4*)&Asr[k][ty * 4];
            float4 a_i = *(const float4*)&Asi[k][ty * 4];
            float4 b_r = *(const float4*)&Bsr[k][tx * 4];
            float4 b_i = *(const float4*)&Bsi[k][tx * 4];
            float ar[4] = {a_r.x, a_r.y, a_r.z, a_r.w};
            float ai[4] = {a_i.x, a_i.y, a_i.z, a_i.w};
            float br[4] = {b_r.x, b_r.y, b_r.z, b_r.w};
            float bi[4] = {b_i.x, b_i.y, b_i.z, b_i.w};
#pragma unroll
            for (int i = 0; i < 4; i++) {
                float nai = -ai[i];
#pragma unroll
                for (int j = 0; j < 4; j++) {
                    accr[i][j] = fmaf(ar[i],  br[j], accr[i][j]);
                    accr[i][j] = fmaf(nai,    bi[j], accr[i][j]);
                    acci[i][j] = fmaf(ar[i],  bi[j], acci[i][j]);
                    acci[i][j] = fmaf(ai[i],  br[j], acci[i][j]);
                }
            }
        }
    }

#pragma unroll
    for (int i = 0; i < 4; i++)
#pragma unroll
        for (int j = 0; j < 4; j++) {
            size_t idx = (size_t)(m0 + ty * 4 + i) * N + (n0 + tx * 4 + j);
            Yr[idx] = accr[i][j];
            Yi[idx] = acci[i][j];
        }
}

// Output projection: reads globals g_or/g_oi, writes interleaved output.
__global__ __launch_bounds__(256) void cgemm_nt_out(
    const float* __restrict__ Wr, const float* __restrict__ Wi,
    float* __restrict__ out)
{
    __shared__ float Asr[16][64], Asi[16][64], Bsr[16][64], Bsi[16][64];
    const int tid = threadIdx.x;
    const int tx = tid & 15, ty = tid >> 4;
    const int m0 = blockIdx.y * 64, n0 = blockIdx.x * 64;
    const int lrow = tid >> 2;
    const int lk   = (tid & 3) * 4;
    const int K = HD_, N = R_;
    const float* Xr = g_or;
    const float* Xi = g_oi;

    float accr[4][4], acci[4][4];
#pragma unroll
    for (int i = 0; i < 4; i++)
#pragma unroll
        for (int j = 0; j < 4; j++) { accr[i][j] = 0.f; acci[i][j] = 0.f; }

    for (int k0 = 0; k0 < K; k0 += 16) {
        float4 xr = *(const float4*)(Xr + (size_t)(m0 + lrow) * K + k0 + lk);
        float4 xi = *(const float4*)(Xi + (size_t)(m0 + lrow) * K + k0 + lk);
        float4 wr = *(const float4*)(Wr + (size_t)(n0 + lrow) * K + k0 + lk);
        float4 wi = *(const float4*)(Wi + (size_t)(n0 + lrow) * K + k0 + lk);
        __syncthreads();
        Asr[lk + 0][lrow] = xr.x; Asr[lk + 1][lrow] = xr.y;
        Asr[lk + 2][lrow] = xr.z; Asr[lk + 3][lrow] = xr.w;
        Asi[lk + 0][lrow] = xi.x; Asi[lk + 1][lrow] = xi.y;
        Asi[lk + 2][lrow] = xi.z; Asi[lk + 3][lrow] = xi.w;
        Bsr[lk + 0][lrow] = wr.x; Bsr[lk + 1][lrow] = wr.y;
        Bsr[lk + 2][lrow] = wr.z; Bsr[lk + 3][lrow] = wr.w;
        Bsi[lk + 0][lrow] = wi.x; Bsi[lk + 1][lrow] = wi.y;
        Bsi[lk + 2][lrow] = wi.z; Bsi[lk + 3][lrow] = wi.w;
        __syncthreads();

#pragma unroll
        for (int k = 0; k < 16; k++) {
            float4 a_r = *(const float4*)&Asr[k][ty * 4];
            float4 a_i = *(const float4*)&Asi[k][ty * 4];
            float4 b_r = *(const float4*)&Bsr[k][tx * 4];
            float4 b_i = *(const float4*)&Bsi[k][tx * 4];
            float ar[4] = {a_r.x, a_r.y, a_r.z, a_r.w};
            float ai[4] = {a_i.x, a_i.y, a_i.z, a_i.w};
            float br[4] = {b_r.x, b_r.y, b_r.z, b_r.w};
            float bi[4] = {b_i.x, b_i.y, b_i.z, b_i.w};
#pragma unroll
            for (int i = 0; i < 4; i++) {
                float nai = -ai[i];
#pragma unroll
                for (int j = 0; j < 4; j++) {
                    accr[i][j] = fmaf(ar[i],  br[j], accr[i][j]);
                    accr[i][j] = fmaf(nai,    bi[j], accr[i][j]);
                    acci[i][j] = fmaf(ar[i],  bi[j], acci[i][j]);
                    acci[i][j] = fmaf(ai[i],  br[j], acci[i][j]);
                }
            }
        }
    }

#pragma unroll
    for (int i = 0; i < 4; i++)
#pragma unroll
        for (int j = 0; j < 4; j++) {
            size_t idx = ((size_t)(m0 + ty * 4 + i) * N + (n0 + tx * 4 + j)) * 2;
            out[idx]     = accr[i][j];
            out[idx + 1] = acci[i][j];
        }
}

// ---------------------------------------------------------------------------
// Launch
// ---------------------------------------------------------------------------
extern "C" void kernel_launch(void* const* d_in, const int* in_sizes, int n_in,
                              void* d_out, int out_size)
{
    const float* Qr   = (const float*)d_in[0];
    const float* Qi   = (const float*)d_in[1];
    const float* Kr   = (const float*)d_in[2];
    const float* Ki   = (const float*)d_in[3];
    const float* Vr   = (const float*)d_in[4];
    const float* Vi   = (const float*)d_in[5];
    const float* wq_r = (const float*)d_in[6];
    const float* wq_i = (const float*)d_in[7];
    const float* wk_r = (const float*)d_in[8];
    const float* wk_i = (const float*)d_in[9];
    const float* wv_r = (const float*)d_in[10];
    const float* wv_i = (const float*)d_in[11];
    const float* wo_r = (const float*)d_in[12];
    const float* wo_i = (const float*)d_in[13];
    float* out = (float*)d_out;

    cudaFuncSetAttribute(cattn_kernel,
                         cudaFuncAttributeMaxDynamicSharedMemorySize, 98304);

    dim3 gb(HD_ / 64, M_ / 64);   // (8, 64)
    dim3 tb(256);

    // Input projections (complex): Q, K, V  -> device-global scratch
    cgemm_nt_proj<<<gb, tb>>>(Qr, Qi, wq_r, wq_i, 0);
    cgemm_nt_proj<<<gb, tb>>>(Kr, Ki, wk_r, wk_i, 1);
    cgemm_nt_proj<<<gb, tb>>>(Vr, Vi, wv_r, wv_i, 2);

    // Fused complex-magnitude flash attention (globals -> globals)
    cattn_kernel<<<dim3(NQ_ / 64, B_ * H_), tb, 98304>>>();

    // Output projection (complex), interleaved (B, NQ, R, 2)
    cgemm_nt_out<<<dim3(R_ / 64, M_ / 64), tb>>>(wo_r, wo_i, out);
}

// round 4
// speedup vs baseline: 1.0513x; 1.0513x over previous
#include <cuda_runtime.h>
#include <math_constants.h>

// Problem constants
#define B_   2
#define NQ_  2048
#define NK_  2048
#define R_   512
#define H_   8
#define D_   64
#define HD_  512
#define M_   (B_ * NQ_)   // 4096 rows for all projection GEMMs

typedef unsigned long long u64;

// ---------------------------------------------------------------------------
// Packed f32x2 helpers (Blackwell paired-FP32 datapath; PTX-only)
// ---------------------------------------------------------------------------
__device__ __forceinline__ u64 pk2(float x, float y) {
    u64 r; asm("mov.b64 %0, {%1,%2};" : "=l"(r) : "f"(x), "f"(y)); return r;
}
__device__ __forceinline__ u64 bc2(float x) { return pk2(x, x); }
__device__ __forceinline__ void fma2(u64& d, u64 a, u64 b) {
    asm("fma.rn.f32x2 %0, %1, %2, %0;" : "+l"(d) : "l"(a), "l"(b));
}
__device__ __forceinline__ u64 mul2(u64 a, u64 b) {
    u64 r; asm("mul.rn.f32x2 %0, %1, %2;" : "=l"(r) : "l"(a), "l"(b)); return r;
}
__device__ __forceinline__ float2 up2(u64 v) {
    float lo, hi;
    asm("mov.b64 {%0,%1}, %2;" : "=f"(lo), "=f"(hi) : "l"(v));
    return make_float2(lo, hi);
}
__device__ __forceinline__ u64 neg2(u64 a) { return a ^ 0x8000000080000000ULL; }
__device__ __forceinline__ u64 lds64(const float* p) {
    return *(const u64*)p;
}

// ---------------------------------------------------------------------------
// Scratch (device globals; no allocations allowed)
// ---------------------------------------------------------------------------
__device__ float g_qr[M_ * HD_];
__device__ float g_qi[M_ * HD_];
__device__ float g_kr[M_ * HD_];
__device__ float g_ki[M_ * HD_];
__device__ float g_vr[M_ * HD_];
__device__ float g_vi[M_ * HD_];
__device__ float g_or[M_ * HD_];
__device__ float g_oi[M_ * HD_];

// ---------------------------------------------------------------------------
// Complex GEMM core with f32x2 inner loop.
//   Yr = Xr Wr^T - Xi Wi^T ;  Yi = Xr Wi^T + Xi Wr^T
// Accumulators paired over j (2 columns per u64) -> same reg count as fp32.
// ---------------------------------------------------------------------------
template <int ES>
__device__ __forceinline__ void cgemm_body(
    const float* __restrict__ Xr, const float* __restrict__ Xi,
    const float* __restrict__ Wr, const float* __restrict__ Wi,
    float* __restrict__ Yr, float* __restrict__ Yi,
    int N, int K)
{
    __shared__ float Asr[16][64], Asi[16][64], Bsr[16][64], Bsi[16][64];

    const int tid = threadIdx.x;
    const int tx = tid & 15, ty = tid >> 4;
    const int m0 = blockIdx.y * 64, n0 = blockIdx.x * 64;
    const int lrow = tid >> 2;          // 0..63
    const int lk   = (tid & 3) * 4;     // 0,4,8,12

    u64 ar2[4][2], ai2[4][2];           // paired accumulators {j, j+1}
#pragma unroll
    for (int i = 0; i < 4; i++)
#pragma unroll
        for (int p = 0; p < 2; p++) { ar2[i][p] = 0ULL; ai2[i][p] = 0ULL; }

    for (int k0 = 0; k0 < K; k0 += 16) {
        float4 xr = *(const float4*)(Xr + (size_t)(m0 + lrow) * K + k0 + lk);
        float4 xi = *(const float4*)(Xi + (size_t)(m0 + lrow) * K + k0 + lk);
        float4 wr = *(const float4*)(Wr + (size_t)(n0 + lrow) * K + k0 + lk);
        float4 wi = *(const float4*)(Wi + (size_t)(n0 + lrow) * K + k0 + lk);
        __syncthreads();
        Asr[lk + 0][lrow] = xr.x; Asr[lk + 1][lrow] = xr.y;
        Asr[lk + 2][lrow] = xr.z; Asr[lk + 3][lrow] = xr.w;
        Asi[lk + 0][lrow] = xi.x; Asi[lk + 1][lrow] = xi.y;
        Asi[lk + 2][lrow] = xi.z; Asi[lk + 3][lrow] = xi.w;
        Bsr[lk + 0][lrow] = wr.x; Bsr[lk + 1][lrow] = wr.y;
        Bsr[lk + 2][lrow] = wr.z; Bsr[lk + 3][lrow] = wr.w;
        Bsi[lk + 0][lrow] = wi.x; Bsi[lk + 1][lrow] = wi.y;
        Bsi[lk + 2][lrow] = wi.z; Bsi[lk + 3][lrow] = wi.w;
        __syncthreads();

#pragma unroll
        for (int k = 0; k < 16; k++) {
            float4 a_r = *(const float4*)&Asr[k][ty * 4];
            float4 a_i = *(const float4*)&Asi[k][ty * 4];
            u64 br0 = lds64(&Bsr[k][tx * 4]);
            u64 br1 = lds64(&Bsr[k][tx * 4 + 2]);
            u64 bi0 = lds64(&Bsi[k][tx * 4]);
            u64 bi1 = lds64(&Bsi[k][tx * 4 + 2]);
            u64 nbi0 = neg2(bi0), nbi1 = neg2(bi1);
            float arr[4] = {a_r.x, a_r.y, a_r.z, a_r.w};
            float aii[4] = {a_i.x, a_i.y, a_i.z, a_i.w};
#pragma unroll
            for (int i = 0; i < 4; i++) {
                u64 a2r = bc2(arr[i]);
                u64 a2i = bc2(aii[i]);
                fma2(ar2[i][0], a2r, br0);  fma2(ar2[i][0], a2i, nbi0);
                fma2(ar2[i][1], a2r, br1);  fma2(ar2[i][1], a2i, nbi1);
                fma2(ai2[i][0], a2r, bi0);  fma2(ai2[i][0], a2i, br0);
                fma2(ai2[i][1], a2r, bi1);  fma2(ai2[i][1], a2i, br1);
            }
        }
    }

#pragma unroll
    for (int i = 0; i < 4; i++) {
        size_t row = (size_t)(m0 + ty * 4 + i) * N;
#pragma unroll
        for (int p = 0; p < 2; p++) {
            float2 vr = up2(ar2[i][p]);
            float2 vi = up2(ai2[i][p]);
            size_t c = row + n0 + tx * 4 + p * 2;
            Yr[c * ES]       = vr.x;
            Yi[c * ES]       = vi.x;
            Yr[(c + 1) * ES] = vr.y;
            Yi[(c + 1) * ES] = vi.y;
        }
    }
}

// Q/K/V projections -> device-global scratch (selected by id).
__global__ __launch_bounds__(256) void cgemm_nt_proj(
    const float* __restrict__ Xr, const float* __restrict__ Xi,
    const float* __restrict__ Wr, const float* __restrict__ Wi,
    int which)   // 0 = Q, 1 = K, 2 = V
{
    float* Yr = (which == 0) ? g_qr : (which == 1) ? g_kr : g_vr;
    float* Yi = (which == 0) ? g_qi : (which == 1) ? g_ki : g_vi;
    cgemm_body<1>(Xr, Xi, Wr, Wi, Yr, Yi, HD_, R_);
}

// Output projection: reads globals, writes interleaved (B, NQ, R, 2).
__global__ __launch_bounds__(256) void cgemm_nt_out(
    const float* __restrict__ Wr, const float* __restrict__ Wi,
    float* __restrict__ out)
{
    cgemm_body<2>(g_or, g_oi, Wr, Wi, out, out + 1, R_, HD_);
}

// ---------------------------------------------------------------------------
// Fused complex-magnitude flash attention (fp32, f32x2 inner loops).
// Per block: one (b, h), one 64-row q tile. Loops over 32 k tiles of 64.
//   s_re = Qr.Kr + Qi.Ki ; s_im = Qi.Kr - Qr.Ki
//   mag = |s| * (1/8) ; online softmax over mag ; O(+re/+im) = P @ V
// Smem (dynamic, 96 KB): Qr,Qi,Kr,Ki (all [d][n] transposed), Vr,Vi ([n][d]).
// P tile reuses the Kr buffer after scores are consumed.
// ---------------------------------------------------------------------------
__global__ __launch_bounds__(256, 2) void cattn_kernel()
{
    extern __shared__ float sm[];
    float* sQr = sm;            // [64][64]  (d-major)
    float* sQi = sm + 4096;
    float* sKr = sm + 8192;     // [64][64]  (d-major); reused as P [m][n]
    float* sKi = sm + 12288;
    float* sVr = sm + 16384;    // [64][64]  (n-major)
    float* sVi = sm + 20480;
    float* sP  = sKr;

    const int tid = threadIdx.x;
    const int tx = tid & 15, ty = tid >> 4;
    const int q0 = blockIdx.x * 64;
    const int bh = blockIdx.y;
    const int b  = bh >> 3, h = bh & 7;
    const int col0 = h * D_;

    const int lrow = tid >> 2;          // 0..63
    const int lc   = (tid & 3) * 16;    // 0,16,32,48

    // --- Load Q tile (transposed into [d][m]) ---
    {
        const float* qr = g_qr + (size_t)(b * NQ_ + q0 + lrow) * HD_ + col0;
        const float* qi = g_qi + (size_t)(b * NQ_ + q0 + lrow) * HD_ + col0;
#pragma unroll
        for (int u = 0; u < 4; u++) {
            int d = lc + u * 4;
            float4 fr = *(const float4*)(qr + d);
            float4 fi = *(const float4*)(qi + d);
            sQr[(d + 0) * 64 + lrow] = fr.x; sQr[(d + 1) * 64 + lrow] = fr.y;
            sQr[(d + 2) * 64 + lrow] = fr.z; sQr[(d + 3) * 64 + lrow] = fr.w;
            sQi[(d + 0) * 64 + lrow] = fi.x; sQi[(d + 1) * 64 + lrow] = fi.y;
            sQi[(d + 2) * 64 + lrow] = fi.z; sQi[(d + 3) * 64 + lrow] = fi.w;
        }
    }

    float mi[4], li[4];
    u64 o2r[4][2], o2i[4][2];           // paired over d-columns {j, j+1}
#pragma unroll
    for (int i = 0; i < 4; i++) {
        mi[i] = -CUDART_INF_F; li[i] = 0.f;
#pragma unroll
        for (int p = 0; p < 2; p++) { o2r[i][p] = 0ULL; o2i[i][p] = 0ULL; }
    }

    for (int nt = 0; nt < NK_ / 64; nt++) {
        const int n0 = nt * 64;
        const size_t rowbase = (size_t)(b * NK_ + n0 + lrow) * HD_ + col0;
        const float* kr = g_kr + rowbase;
        const float* ki = g_ki + rowbase;
        const float* vr = g_vr + rowbase;
        const float* vi = g_vi + rowbase;

        __syncthreads();   // previous iteration finished reading sP/sV
#pragma unroll
        for (int u = 0; u < 4; u++) {
            int d = lc + u * 4;
            float4 fr = *(const float4*)(kr + d);
            float4 fi = *(const float4*)(ki + d);
            sKr[(d + 0) * 64 + lrow] = fr.x; sKr[(d + 1) * 64 + lrow] = fr.y;
            sKr[(d + 2) * 64 + lrow] = fr.z; sKr[(d + 3) * 64 + lrow] = fr.w;
            sKi[(d + 0) * 64 + lrow] = fi.x; sKi[(d + 1) * 64 + lrow] = fi.y;
            sKi[(d + 2) * 64 + lrow] = fi.z; sKi[(d + 3) * 64 + lrow] = fi.w;
            *(float4*)&sVr[lrow * 64 + d] = *(const float4*)(vr + d);
            *(float4*)&sVi[lrow * 64 + d] = *(const float4*)(vi + d);
        }
        __syncthreads();

        // --- scores: 4 rows x (2x2-paired) cols per thread ---
        u64 sre2[4][2], sim2[4][2];
#pragma unroll
        for (int i = 0; i < 4; i++)
#pragma unroll
            for (int p = 0; p < 2; p++) { sre2[i][p] = 0ULL; sim2[i][p] = 0ULL; }

#pragma unroll 8
        for (int d = 0; d < 64; d++) {
            float4 q_r = *(const float4*)&sQr[d * 64 + ty * 4];
            float4 q_i = *(const float4*)&sQi[d * 64 + ty * 4];
            u64 kr0 = lds64(&sKr[d * 64 + tx * 4]);
            u64 kr1 = lds64(&sKr[d * 64 + tx * 4 + 2]);
            u64 ki0 = lds64(&sKi[d * 64 + tx * 4]);
            u64 ki1 = lds64(&sKi[d * 64 + tx * 4 + 2]);
            u64 nki0 = neg2(ki0), nki1 = neg2(ki1);
            float qrr[4] = {q_r.x, q_r.y, q_r.z, q_r.w};
            float qii[4] = {q_i.x, q_i.y, q_i.z, q_i.w};
#pragma unroll
            for (int i = 0; i < 4; i++) {
                u64 q2r = bc2(qrr[i]);
                u64 q2i = bc2(qii[i]);
                fma2(sre2[i][0], q2r, kr0);  fma2(sre2[i][0], q2i, ki0);
                fma2(sre2[i][1], q2r, kr1);  fma2(sre2[i][1], q2i, ki1);
                fma2(sim2[i][0], q2i, kr0);  fma2(sim2[i][0], q2r, nki0);
                fma2(sim2[i][1], q2i, kr1);  fma2(sim2[i][1], q2r, nki1);
            }
        }
        __syncthreads();   // done reading sKr/sKi; safe to overwrite with P

        // --- magnitude + online softmax (rows owned by 16-lane groups) ---
#pragma unroll
        for (int i = 0; i < 4; i++) {
            float2 re0 = up2(sre2[i][0]), re1 = up2(sre2[i][1]);
            float2 im0 = up2(sim2[i][0]), im1 = up2(sim2[i][1]);
            float sr[4] = {re0.x, re0.y, re1.x, re1.y};
            float si[4] = {im0.x, im0.y, im1.x, im1.y};
            float p[4];
            float rmax = -CUDART_INF_F;
#pragma unroll
            for (int j = 0; j < 4; j++) {
                float s2 = fmaf(sr[j], sr[j], si[j] * si[j]) + 1e-30f;
                float mag = s2 * rsqrtf(s2) * 0.125f;
                p[j] = mag;
                rmax = fmaxf(rmax, mag);
            }
#pragma unroll
            for (int s = 8; s; s >>= 1)
                rmax = fmaxf(rmax, __shfl_xor_sync(0xffffffffu, rmax, s));
            float mnew  = fmaxf(mi[i], rmax);
            float alpha = __expf(mi[i] - mnew);
            float rsum = 0.f;
#pragma unroll
            for (int j = 0; j < 4; j++) { p[j] = __expf(p[j] - mnew); rsum += p[j]; }
#pragma unroll
            for (int s = 8; s; s >>= 1)
                rsum += __shfl_xor_sync(0xffffffffu, rsum, s);
            li[i] = li[i] * alpha + rsum;
            mi[i] = mnew;
            u64 a2 = bc2(alpha);
            o2r[i][0] = mul2(o2r[i][0], a2);  o2r[i][1] = mul2(o2r[i][1], a2);
            o2i[i][0] = mul2(o2i[i][0], a2);  o2i[i][1] = mul2(o2i[i][1], a2);
            *(float4*)&sP[(ty * 4 + i) * 64 + tx * 4] = make_float4(p[0], p[1], p[2], p[3]);
        }
        __syncthreads();

        // --- O += P @ V (paired over V's d-columns) ---
#pragma unroll 8
        for (int n = 0; n < 64; n++) {
            u64 vr0 = lds64(&sVr[n * 64 + tx * 4]);
            u64 vr1 = lds64(&sVr[n * 64 + tx * 4 + 2]);
            u64 vi0 = lds64(&sVi[n * 64 + tx * 4]);
            u64 vi1 = lds64(&sVi[n * 64 + tx * 4 + 2]);
#pragma unroll
            for (int i = 0; i < 4; i++) {
                u64 pv2 = bc2(sP[(ty * 4 + i) * 64 + n]);
                fma2(o2r[i][0], pv2, vr0);  fma2(o2r[i][1], pv2, vr1);
                fma2(o2i[i][0], pv2, vi0);  fma2(o2i[i][1], pv2, vi1);
            }
        }
    }

    // --- epilogue: O / l, write merged-head layout (b, q, h*64+d) ---
#pragma unroll
    for (int i = 0; i < 4; i++) {
        float inv = 1.0f / li[i];
        float2 r0 = up2(o2r[i][0]), r1 = up2(o2r[i][1]);
        float2 i0 = up2(o2i[i][0]), i1 = up2(o2i[i][1]);
        size_t base = (size_t)(b * NQ_ + q0 + ty * 4 + i) * HD_ + col0 + tx * 4;
        *(float4*)&g_or[base] = make_float4(r0.x * inv, r0.y * inv,
                                            r1.x * inv, r1.y * inv);
        *(float4*)&g_oi[base] = make_float4(i0.x * inv, i0.y * inv,
                                            i1.x * inv, i1.y * inv);
    }
}

// ---------------------------------------------------------------------------
// Launch
// ---------------------------------------------------------------------------
extern "C" void kernel_launch(void* const* d_in, const int* in_sizes, int n_in,
                              void* d_out, int out_size)
{
    const float* Qr   = (const float*)d_in[0];
    const float* Qi   = (const float*)d_in[1];
    const float* Kr   = (const float*)d_in[2];
    const float* Ki   = (const float*)d_in[3];
    const float* Vr   = (const float*)d_in[4];
    const float* Vi   = (const float*)d_in[5];
    const float* wq_r = (const float*)d_in[6];
    const float* wq_i = (const float*)d_in[7];
    const float* wk_r = (const float*)d_in[8];
    const float* wk_i = (const float*)d_in[9];
    const float* wv_r = (const float*)d_in[10];
    const float* wv_i = (const float*)d_in[11];
    const float* wo_r = (const float*)d_in[12];
    const float* wo_i = (const float*)d_in[13];
    float* out = (float*)d_out;

    cudaFuncSetAttribute(cattn_kernel,
                         cudaFuncAttributeMaxDynamicSharedMemorySize, 98304);

    dim3 gb(HD_ / 64, M_ / 64);   // (8, 64)
    dim3 tb(256);

    // Input projections (complex): Q, K, V  -> device-global scratch
    cgemm_nt_proj<<<gb, tb>>>(Qr, Qi, wq_r, wq_i, 0);
    cgemm_nt_proj<<<gb, tb>>>(Kr, Ki, wk_r, wk_i, 1);
    cgemm_nt_proj<<<gb, tb>>>(Vr, Vi, wv_r, wv_i, 2);

    // Fused complex-magnitude flash attention (globals -> globals)
    cattn_kernel<<<dim3(NQ_ / 64, B_ * H_), tb, 98304>>>();

    // Output projection (complex), interleaved (B, NQ, R, 2)
    cgemm_nt_out<<<dim3(R_ / 64, M_ / 64), tb>>>(wo_r, wo_i, out);
}

// round 5
// speedup vs baseline: 1.2827x; 1.2200x over previous
#include <cuda_runtime.h>
#include <cuda_bf16.h>
#include <math_constants.h>

// Problem constants
#define B_   2
#define NQ_  2048
#define NK_  2048
#define R_   512
#define H_   8
#define D_   64
#define HD_  512
#define M_   (B_ * NQ_)   // 4096 rows for all projection GEMMs

typedef unsigned int       u32;
typedef unsigned long long u64;

// ---------------------------------------------------------------------------
// Packed f32x2 helpers (attention kernel)
// ---------------------------------------------------------------------------
__device__ __forceinline__ u64 pk2(float x, float y) {
    u64 r; asm("mov.b64 %0, {%1,%2};" : "=l"(r) : "f"(x), "f"(y)); return r;
}
__device__ __forceinline__ u64 bc2(float x) { return pk2(x, x); }
__device__ __forceinline__ void fma2(u64& d, u64 a, u64 b) {
    asm("fma.rn.f32x2 %0, %1, %2, %0;" : "+l"(d) : "l"(a), "l"(b));
}
__device__ __forceinline__ u64 mul2(u64 a, u64 b) {
    u64 r; asm("mul.rn.f32x2 %0, %1, %2;" : "=l"(r) : "l"(a), "l"(b)); return r;
}
__device__ __forceinline__ float2 up2(u64 v) {
    float lo, hi;
    asm("mov.b64 {%0,%1}, %2;" : "=f"(lo), "=f"(hi) : "l"(v));
    return make_float2(lo, hi);
}
__device__ __forceinline__ u64 neg2(u64 a) { return a ^ 0x8000000080000000ULL; }
__device__ __forceinline__ u64 lds64(const float* p) { return *(const u64*)p; }

// ---------------------------------------------------------------------------
// Scratch (device globals; no allocations allowed)
// ---------------------------------------------------------------------------
__device__ float g_qr[M_ * HD_];
__device__ float g_qi[M_ * HD_];
__device__ float g_kr[M_ * HD_];
__device__ float g_ki[M_ * HD_];
__device__ float g_vr[M_ * HD_];
__device__ float g_vi[M_ * HD_];
__device__ float g_or[M_ * HD_];
__device__ float g_oi[M_ * HD_];

// ---------------------------------------------------------------------------
// bf16 split helpers: x = hi + lo (each bf16), packed as bf16x2 in u32.
// ---------------------------------------------------------------------------
__device__ __forceinline__ void split_pack(float x0, float x1, u32& h, u32& l) {
    __nv_bfloat162 hv = __floats2bfloat162_rn(x0, x1);
    float h0 = __bfloat162float(__low2bfloat16(hv));
    float h1 = __bfloat162float(__high2bfloat16(hv));
    __nv_bfloat162 lv = __floats2bfloat162_rn(x0 - h0, x1 - h1);
    h = *reinterpret_cast<u32*>(&hv);
    l = *reinterpret_cast<u32*>(&lv);
}
__device__ __forceinline__ u32 negbf2(u32 x) { return x ^ 0x80008000u; }

// mma.sync m16n8k16 row.col f32 += bf16 * bf16
__device__ __forceinline__ void mma16816(float* c, const u32* a, const u32* b) {
    asm volatile(
        "mma.sync.aligned.m16n8k16.row.col.f32.bf16.bf16.f32 "
        "{%0,%1,%2,%3}, {%4,%5,%6,%7}, {%8,%9}, {%0,%1,%2,%3};"
        : "+f"(c[0]), "+f"(c[1]), "+f"(c[2]), "+f"(c[3])
        : "r"(a[0]), "r"(a[1]), "r"(a[2]), "r"(a[3]), "r"(b[0]), "r"(b[1]));
}

// ---------------------------------------------------------------------------
// Tensor-core complex GEMM with bf16 2-term split precision.
//   Yr = Xr Wr^T - Xi Wi^T ;  Yi = Xr Wi^T + Xi Wr^T
// X: (M, K) f32 row-major; W: (N, K) f32 row-major. Both converted to
// (hi, lo) bf16 in shared memory on the fly.
// Block: 256 thr (8 warps), tile BM=128 x BN=64, K-chunk 32.
// Warp grid 4(m) x 2(n); warp tile 32x32 = 2 x 4 mma tiles (m16n8).
// Per k16 and output plane pair: 12 MMAs (3-term split x complex).
// ---------------------------------------------------------------------------
#define APITCH 17            // u32 pitch for 16 k-pairs + 1 pad
#define A_SZ   (128 * APITCH)
#define B_SZ   (64  * APITCH)

template <int ES>
__device__ __forceinline__ void cgemm_ts_body(
    const float* __restrict__ Xr, const float* __restrict__ Xi,
    const float* __restrict__ Wr, const float* __restrict__ Wi,
    float* __restrict__ Yr, float* __restrict__ Yi,
    int N, int K)
{
    extern __shared__ u32 dsm[];
    u32* sArh = dsm;
    u32* sArl = dsm + A_SZ;
    u32* sAih = dsm + 2 * A_SZ;
    u32* sAil = dsm + 3 * A_SZ;
    u32* sBrh = dsm + 4 * A_SZ;
    u32* sBrl = dsm + 4 * A_SZ + B_SZ;
    u32* sBih = dsm + 4 * A_SZ + 2 * B_SZ;
    u32* sBil = dsm + 4 * A_SZ + 3 * B_SZ;

    const int tid  = threadIdx.x;
    const int lane = tid & 31;
    const int wid  = tid >> 5;
    const int wm   = wid & 3;          // 0..3 (m sub-block of 32 rows)
    const int wn   = wid >> 2;         // 0..1 (n sub-block of 32 cols)
    const int g    = lane >> 2;        // 0..7
    const int tg   = lane & 3;         // 0..3

    const int m0 = blockIdx.y * 128;
    const int n0 = blockIdx.x * 64;

    // A staging map: 2 threads per row, 4 float4 segs each
    const int arow = tid >> 1;
    const int aseg = (tid & 1) * 4;
    // B staging map: 4 threads per row, 2 float4 segs each
    const int brow = tid >> 2;
    const int bseg = (tid & 3) * 2;

    float yr[2][4][4], yi[2][4][4];
#pragma unroll
    for (int mt = 0; mt < 2; mt++)
#pragma unroll
        for (int nt = 0; nt < 4; nt++)
#pragma unroll
            for (int c = 0; c < 4; c++) { yr[mt][nt][c] = 0.f; yi[mt][nt][c] = 0.f; }

    for (int k0 = 0; k0 < K; k0 += 32) {
        __syncthreads();
        // --- stage A (Xr, Xi) with split conversion ---
        {
            const float* pr = Xr + (size_t)(m0 + arow) * K + k0;
            const float* pi = Xi + (size_t)(m0 + arow) * K + k0;
#pragma unroll
            for (int s = 0; s < 4; s++) {
                int seg = aseg + s;
                float4 v = *(const float4*)(pr + seg * 4);
                u32 h0, l0, h1, l1;
                split_pack(v.x, v.y, h0, l0);
                split_pack(v.z, v.w, h1, l1);
                sArh[arow * APITCH + seg * 2]     = h0;
                sArh[arow * APITCH + seg * 2 + 1] = h1;
                sArl[arow * APITCH + seg * 2]     = l0;
                sArl[arow * APITCH + seg * 2 + 1] = l1;
                v = *(const float4*)(pi + seg * 4);
                split_pack(v.x, v.y, h0, l0);
                split_pack(v.z, v.w, h1, l1);
                sAih[arow * APITCH + seg * 2]     = h0;
                sAih[arow * APITCH + seg * 2 + 1] = h1;
                sAil[arow * APITCH + seg * 2]     = l0;
                sAil[arow * APITCH + seg * 2 + 1] = l1;
            }
        }
        // --- stage B (Wr, Wi) with split conversion ---
        {
            const float* pr = Wr + (size_t)(n0 + brow) * K + k0;
            const float* pi = Wi + (size_t)(n0 + brow) * K + k0;
#pragma unroll
            for (int s = 0; s < 2; s++) {
                int seg = bseg + s;
                float4 v = *(const float4*)(pr + seg * 4);
                u32 h0, l0, h1, l1;
                split_pack(v.x, v.y, h0, l0);
                split_pack(v.z, v.w, h1, l1);
                sBrh[brow * APITCH + seg * 2]     = h0;
                sBrh[brow * APITCH + seg * 2 + 1] = h1;
                sBrl[brow * APITCH + seg * 2]     = l0;
                sBrl[brow * APITCH + seg * 2 + 1] = l1;
                v = *(const float4*)(pi + seg * 4);
                split_pack(v.x, v.y, h0, l0);
                split_pack(v.z, v.w, h1, l1);
                sBih[brow * APITCH + seg * 2]     = h0;
                sBih[brow * APITCH + seg * 2 + 1] = h1;
                sBil[brow * APITCH + seg * 2]     = l0;
                sBil[brow * APITCH + seg * 2 + 1] = l1;
            }
        }
        __syncthreads();

#pragma unroll
        for (int ks = 0; ks < 2; ks++) {
            const int cb = ks * 8;
            // A fragments for both m-tiles (4 arrays x 4 regs)
            u32 fArh[2][4], fArl[2][4], fAih[2][4], fAil[2][4];
#pragma unroll
            for (int mt = 0; mt < 2; mt++) {
                int r0 = wm * 32 + mt * 16 + g;
                int i00 = r0 * APITCH + cb + tg;
                int i08 = (r0 + 8) * APITCH + cb + tg;
                fArh[mt][0] = sArh[i00]; fArh[mt][1] = sArh[i08];
                fArh[mt][2] = sArh[i00 + 4]; fArh[mt][3] = sArh[i08 + 4];
                fArl[mt][0] = sArl[i00]; fArl[mt][1] = sArl[i08];
                fArl[mt][2] = sArl[i00 + 4]; fArl[mt][3] = sArl[i08 + 4];
                fAih[mt][0] = sAih[i00]; fAih[mt][1] = sAih[i08];
                fAih[mt][2] = sAih[i00 + 4]; fAih[mt][3] = sAih[i08 + 4];
                fAil[mt][0] = sAil[i00]; fAil[mt][1] = sAil[i08];
                fAil[mt][2] = sAil[i00 + 4]; fAil[mt][3] = sAil[i08 + 4];
            }
#pragma unroll
            for (int nt = 0; nt < 4; nt++) {
                int cn = wn * 32 + nt * 8 + g;
                int j0 = cn * APITCH + cb + tg;
                u32 fBrh[2] = { sBrh[j0], sBrh[j0 + 4] };
                u32 fBrl[2] = { sBrl[j0], sBrl[j0 + 4] };
                u32 fBih[2] = { sBih[j0], sBih[j0 + 4] };
                u32 fBil[2] = { sBil[j0], sBil[j0 + 4] };
                u32 fBihN[2] = { negbf2(fBih[0]), negbf2(fBih[1]) };
                u32 fBilN[2] = { negbf2(fBil[0]), negbf2(fBil[1]) };
#pragma unroll
                for (int mt = 0; mt < 2; mt++) {
                    // Yr = Xr*Wr - Xi*Wi (3-term split each)
                    mma16816(yr[mt][nt], fArh[mt], fBrh);
                    mma16816(yr[mt][nt], fArl[mt], fBrh);
                    mma16816(yr[mt][nt], fArh[mt], fBrl);
                    mma16816(yr[mt][nt], fAih[mt], fBihN);
                    mma16816(yr[mt][nt], fAil[mt], fBihN);
                    mma16816(yr[mt][nt], fAih[mt], fBilN);
                    // Yi = Xr*Wi + Xi*Wr
                    mma16816(yi[mt][nt], fArh[mt], fBih);
                    mma16816(yi[mt][nt], fArl[mt], fBih);
                    mma16816(yi[mt][nt], fArh[mt], fBil);
                    mma16816(yi[mt][nt], fAih[mt], fBrh);
                    mma16816(yi[mt][nt], fAil[mt], fBrh);
                    mma16816(yi[mt][nt], fAih[mt], fBrl);
                }
            }
        }
    }

    // --- epilogue: write C fragments ---
#pragma unroll
    for (int mt = 0; mt < 2; mt++) {
#pragma unroll
        for (int nt = 0; nt < 4; nt++) {
            int row = m0 + wm * 32 + mt * 16 + g;
            int col = n0 + wn * 32 + nt * 8 + tg * 2;
            size_t i0 = ((size_t)row * N + col) * ES;
            size_t i1 = ((size_t)(row + 8) * N + col) * ES;
            Yr[i0]      = yr[mt][nt][0];
            Yr[i0 + ES] = yr[mt][nt][1];
            Yi[i0]      = yi[mt][nt][0];
            Yi[i0 + ES] = yi[mt][nt][1];
            Yr[i1]      = yr[mt][nt][2];
            Yr[i1 + ES] = yr[mt][nt][3];
            Yi[i1]      = yi[mt][nt][2];
            Yi[i1 + ES] = yi[mt][nt][3];
        }
    }
}

#define GEMM_SMEM ((4 * A_SZ + 4 * B_SZ) * 4)

// Q/K/V projections -> device-global scratch (selected by id).
__global__ __launch_bounds__(256, 1) void cgemm_ts_proj(
    const float* __restrict__ Xr, const float* __restrict__ Xi,
    const float* __restrict__ Wr, const float* __restrict__ Wi,
    int which)   // 0 = Q, 1 = K, 2 = V
{
    float* Yr = (which == 0) ? g_qr : (which == 1) ? g_kr : g_vr;
    float* Yi = (which == 0) ? g_qi : (which == 1) ? g_ki : g_vi;
    cgemm_ts_body<1>(Xr, Xi, Wr, Wi, Yr, Yi, HD_, R_);
}

// Output projection: reads globals, writes interleaved (B, NQ, R, 2).
__global__ __launch_bounds__(256, 1) void cgemm_ts_out(
    const float* __restrict__ Wr, const float* __restrict__ Wi,
    float* __restrict__ out)
{
    cgemm_ts_body<2>(g_or, g_oi, Wr, Wi, out, out + 1, R_, HD_);
}

// ---------------------------------------------------------------------------
// Fused complex-magnitude flash attention (fp32, f32x2 inner loops).
// (unchanged from previous passing round)
// ---------------------------------------------------------------------------
__global__ __launch_bounds__(256, 2) void cattn_kernel()
{
    extern __shared__ float sm[];
    float* sQr = sm;            // [64][64]  (d-major)
    float* sQi = sm + 4096;
    float* sKr = sm + 8192;     // [64][64]  (d-major); reused as P [m][n]
    float* sKi = sm + 12288;
    float* sVr = sm + 16384;    // [64][64]  (n-major)
    float* sVi = sm + 20480;
    float* sP  = sKr;

    const int tid = threadIdx.x;
    const int tx = tid & 15, ty = tid >> 4;
    const int q0 = blockIdx.x * 64;
    const int bh = blockIdx.y;
    const int b  = bh >> 3, h = bh & 7;
    const int col0 = h * D_;

    const int lrow = tid >> 2;          // 0..63
    const int lc   = (tid & 3) * 16;    // 0,16,32,48

    {
        const float* qr = g_qr + (size_t)(b * NQ_ + q0 + lrow) * HD_ + col0;
        const float* qi = g_qi + (size_t)(b * NQ_ + q0 + lrow) * HD_ + col0;
#pragma unroll
        for (int u = 0; u < 4; u++) {
            int d = lc + u * 4;
            float4 fr = *(const float4*)(qr + d);
            float4 fi = *(const float4*)(qi + d);
            sQr[(d + 0) * 64 + lrow] = fr.x; sQr[(d + 1) * 64 + lrow] = fr.y;
            sQr[(d + 2) * 64 + lrow] = fr.z; sQr[(d + 3) * 64 + lrow] = fr.w;
            sQi[(d + 0) * 64 + lrow] = fi.x; sQi[(d + 1) * 64 + lrow] = fi.y;
            sQi[(d + 2) * 64 + lrow] = fi.z; sQi[(d + 3) * 64 + lrow] = fi.w;
        }
    }

    float mi[4], li[4];
    u64 o2r[4][2], o2i[4][2];
#pragma unroll
    for (int i = 0; i < 4; i++) {
        mi[i] = -CUDART_INF_F; li[i] = 0.f;
#pragma unroll
        for (int p = 0; p < 2; p++) { o2r[i][p] = 0ULL; o2i[i][p] = 0ULL; }
    }

    for (int nt = 0; nt < NK_ / 64; nt++) {
        const int n0 = nt * 64;
        const size_t rowbase = (size_t)(b * NK_ + n0 + lrow) * HD_ + col0;
        const float* kr = g_kr + rowbase;
        const float* ki = g_ki + rowbase;
        const float* vr = g_vr + rowbase;
        const float* vi = g_vi + rowbase;

        __syncthreads();
#pragma unroll
        for (int u = 0; u < 4; u++) {
            int d = lc + u * 4;
            float4 fr = *(const float4*)(kr + d);
            float4 fi = *(const float4*)(ki + d);
            sKr[(d + 0) * 64 + lrow] = fr.x; sKr[(d + 1) * 64 + lrow] = fr.y;
            sKr[(d + 2) * 64 + lrow] = fr.z; sKr[(d + 3) * 64 + lrow] = fr.w;
            sKi[(d + 0) * 64 + lrow] = fi.x; sKi[(d + 1) * 64 + lrow] = fi.y;
            sKi[(d + 2) * 64 + lrow] = fi.z; sKi[(d + 3) * 64 + lrow] = fi.w;
            *(float4*)&sVr[lrow * 64 + d] = *(const float4*)(vr + d);
            *(float4*)&sVi[lrow * 64 + d] = *(const float4*)(vi + d);
        }
        __syncthreads();

        u64 sre2[4][2], sim2[4][2];
#pragma unroll
        for (int i = 0; i < 4; i++)
#pragma unroll
            for (int p = 0; p < 2; p++) { sre2[i][p] = 0ULL; sim2[i][p] = 0ULL; }

#pragma unroll 8
        for (int d = 0; d < 64; d++) {
            float4 q_r = *(const float4*)&sQr[d * 64 + ty * 4];
            float4 q_i = *(const float4*)&sQi[d * 64 + ty * 4];
            u64 kr0 = lds64(&sKr[d * 64 + tx * 4]);
            u64 kr1 = lds64(&sKr[d * 64 + tx * 4 + 2]);
            u64 ki0 = lds64(&sKi[d * 64 + tx * 4]);
            u64 ki1 = lds64(&sKi[d * 64 + tx * 4 + 2]);
            u64 nki0 = neg2(ki0), nki1 = neg2(ki1);
            float qrr[4] = {q_r.x, q_r.y, q_r.z, q_r.w};
            float qii[4] = {q_i.x, q_i.y, q_i.z, q_i.w};
#pragma unroll
            for (int i = 0; i < 4; i++) {
                u64 q2r = bc2(qrr[i]);
                u64 q2i = bc2(qii[i]);
                fma2(sre2[i][0], q2r, kr0);  fma2(sre2[i][0], q2i, ki0);
                fma2(sre2[i][1], q2r, kr1);  fma2(sre2[i][1], q2i, ki1);
                fma2(sim2[i][0], q2i, kr0);  fma2(sim2[i][0], q2r, nki0);
                fma2(sim2[i][1], q2i, kr1);  fma2(sim2[i][1], q2r, nki1);
            }
        }
        __syncthreads();

#pragma unroll
        for (int i = 0; i < 4; i++) {
            float2 re0 = up2(sre2[i][0]), re1 = up2(sre2[i][1]);
            float2 im0 = up2(sim2[i][0]), im1 = up2(sim2[i][1]);
            float sr[4] = {re0.x, re0.y, re1.x, re1.y};
            float si[4] = {im0.x, im0.y, im1.x, im1.y};
            float p[4];
            float rmax = -CUDART_INF_F;
#pragma unroll
            for (int j = 0; j < 4; j++) {
                float s2 = fmaf(sr[j], sr[j], si[j] * si[j]) + 1e-30f;
                float mag = s2 * rsqrtf(s2) * 0.125f;
                p[j] = mag;
                rmax = fmaxf(rmax, mag);
            }
#pragma unroll
            for (int s = 8; s; s >>= 1)
                rmax = fmaxf(rmax, __shfl_xor_sync(0xffffffffu, rmax, s));
            float mnew  = fmaxf(mi[i], rmax);
            float alpha = __expf(mi[i] - mnew);
            float rsum = 0.f;
#pragma unroll
            for (int j = 0; j < 4; j++) { p[j] = __expf(p[j] - mnew); rsum += p[j]; }
#pragma unroll
            for (int s = 8; s; s >>= 1)
                rsum += __shfl_xor_sync(0xffffffffu, rsum, s);
            li[i] = li[i] * alpha + rsum;
            mi[i] = mnew;
            u64 a2 = bc2(alpha);
            o2r[i][0] = mul2(o2r[i][0], a2);  o2r[i][1] = mul2(o2r[i][1], a2);
            o2i[i][0] = mul2(o2i[i][0], a2);  o2i[i][1] = mul2(o2i[i][1], a2);
            *(float4*)&sP[(ty * 4 + i) * 64 + tx * 4] = make_float4(p[0], p[1], p[2], p[3]);
        }
        __syncthreads();

#pragma unroll 8
        for (int n = 0; n < 64; n++) {
            u64 vr0 = lds64(&sVr[n * 64 + tx * 4]);
            u64 vr1 = lds64(&sVr[n * 64 + tx * 4 + 2]);
            u64 vi0 = lds64(&sVi[n * 64 + tx * 4]);
            u64 vi1 = lds64(&sVi[n * 64 + tx * 4 + 2]);
#pragma unroll
            for (int i = 0; i < 4; i++) {
                u64 pv2 = bc2(sP[(ty * 4 + i) * 64 + n]);
                fma2(o2r[i][0], pv2, vr0);  fma2(o2r[i][1], pv2, vr1);
                fma2(o2i[i][0], pv2, vi0);  fma2(o2i[i][1], pv2, vi1);
            }
        }
    }

#pragma unroll
    for (int i = 0; i < 4; i++) {
        float inv = 1.0f / li[i];
        float2 r0 = up2(o2r[i][0]), r1 = up2(o2r[i][1]);
        float2 i0 = up2(o2i[i][0]), i1 = up2(o2i[i][1]);
        size_t base = (size_t)(b * NQ_ + q0 + ty * 4 + i) * HD_ + col0 + tx * 4;
        *(float4*)&g_or[base] = make_float4(r0.x * inv, r0.y * inv,
                                            r1.x * inv, r1.y * inv);
        *(float4*)&g_oi[base] = make_float4(i0.x * inv, i0.y * inv,
                                            i1.x * inv, i1.y * inv);
    }
}

// ---------------------------------------------------------------------------
// Launch
// ---------------------------------------------------------------------------
extern "C" void kernel_launch(void* const* d_in, const int* in_sizes, int n_in,
                              void* d_out, int out_size)
{
    const float* Qr   = (const float*)d_in[0];
    const float* Qi   = (const float*)d_in[1];
    const float* Kr   = (const float*)d_in[2];
    const float* Ki   = (const float*)d_in[3];
    const float* Vr   = (const float*)d_in[4];
    const float* Vi   = (const float*)d_in[5];
    const float* wq_r = (const float*)d_in[6];
    const float* wq_i = (const float*)d_in[7];
    const float* wk_r = (const float*)d_in[8];
    const float* wk_i = (const float*)d_in[9];
    const float* wv_r = (const float*)d_in[10];
    const float* wv_i = (const float*)d_in[11];
    const float* wo_r = (const float*)d_in[12];
    const float* wo_i = (const float*)d_in[13];
    float* out = (float*)d_out;

    cudaFuncSetAttribute(cattn_kernel,
                         cudaFuncAttributeMaxDynamicSharedMemorySize, 98304);
    cudaFuncSetAttribute(cgemm_ts_proj,
                         cudaFuncAttributeMaxDynamicSharedMemorySize, GEMM_SMEM);
    cudaFuncSetAttribute(cgemm_ts_out,
                         cudaFuncAttributeMaxDynamicSharedMemorySize, GEMM_SMEM);

    dim3 gb(HD_ / 64, M_ / 128);   // (8, 32)
    dim3 tb(256);

    // Input projections (complex, tensor cores): Q, K, V -> scratch
    cgemm_ts_proj<<<gb, tb, GEMM_SMEM>>>(Qr, Qi, wq_r, wq_i, 0);
    cgemm_ts_proj<<<gb, tb, GEMM_SMEM>>>(Kr, Ki, wk_r, wk_i, 1);
    cgemm_ts_proj<<<gb, tb, GEMM_SMEM>>>(Vr, Vi, wv_r, wv_i, 2);

    // Fused complex-magnitude flash attention (globals -> globals)
    cattn_kernel<<<dim3(NQ_ / 64, B_ * H_), tb, 98304>>>();

    // Output projection (complex, tensor cores), interleaved (B, NQ, R, 2)
    cgemm_ts_out<<<dim3(R_ / 64, M_ / 128), tb, GEMM_SMEM>>>(wo_r, wo_i, out);
}

// round 6
// speedup vs baseline: 1.4275x; 1.1129x over previous
#include <cuda_runtime.h>
#include <cuda_bf16.h>
#include <math_constants.h>

// Problem constants
#define B_   2
#define NQ_  2048
#define NK_  2048
#define R_   512
#define H_   8
#define D_   64
#define HD_  512
#define M_   (B_ * NQ_)   // 4096 rows for all projection GEMMs

typedef unsigned int       u32;
typedef unsigned long long u64;

// ---------------------------------------------------------------------------
// Scratch (device globals; no allocations allowed)
// ---------------------------------------------------------------------------
__device__ float g_qr[M_ * HD_];
__device__ float g_qi[M_ * HD_];
__device__ float g_kr[M_ * HD_];
__device__ float g_ki[M_ * HD_];
__device__ float g_vr[M_ * HD_];
__device__ float g_vi[M_ * HD_];
__device__ float g_or[M_ * HD_];
__device__ float g_oi[M_ * HD_];

// ---------------------------------------------------------------------------
// bf16 split helpers: x = hi + lo (each bf16), packed as bf16x2 in u32.
// ---------------------------------------------------------------------------
__device__ __forceinline__ void split_pack(float x0, float x1, u32& h, u32& l) {
    __nv_bfloat162 hv = __floats2bfloat162_rn(x0, x1);
    float h0 = __bfloat162float(__low2bfloat16(hv));
    float h1 = __bfloat162float(__high2bfloat16(hv));
    __nv_bfloat162 lv = __floats2bfloat162_rn(x0 - h0, x1 - h1);
    h = *reinterpret_cast<u32*>(&hv);
    l = *reinterpret_cast<u32*>(&lv);
}
__device__ __forceinline__ u32 negbf2(u32 x) { return x ^ 0x80008000u; }

// mma.sync m16n8k16 row.col f32 += bf16 * bf16
__device__ __forceinline__ void mma16816(float* c, const u32* a, const u32* b) {
    asm volatile(
        "mma.sync.aligned.m16n8k16.row.col.f32.bf16.bf16.f32 "
        "{%0,%1,%2,%3}, {%4,%5,%6,%7}, {%8,%9}, {%0,%1,%2,%3};"
        : "+f"(c[0]), "+f"(c[1]), "+f"(c[2]), "+f"(c[3])
        : "r"(a[0]), "r"(a[1]), "r"(a[2]), "r"(a[3]), "r"(b[0]), "r"(b[1]));
}

// ---------------------------------------------------------------------------
// Tensor-core complex GEMM with bf16 2-term split precision (as validated R5).
// ---------------------------------------------------------------------------
#define APITCH 17            // u32 pitch for 16 k-pairs + 1 pad
#define A_SZ   (128 * APITCH)
#define B_SZ   (64  * APITCH)

template <int ES>
__device__ __forceinline__ void cgemm_ts_body(
    const float* __restrict__ Xr, const float* __restrict__ Xi,
    const float* __restrict__ Wr, const float* __restrict__ Wi,
    float* __restrict__ Yr, float* __restrict__ Yi,
    int N, int K)
{
    extern __shared__ u32 dsm[];
    u32* sArh = dsm;
    u32* sArl = dsm + A_SZ;
    u32* sAih = dsm + 2 * A_SZ;
    u32* sAil = dsm + 3 * A_SZ;
    u32* sBrh = dsm + 4 * A_SZ;
    u32* sBrl = dsm + 4 * A_SZ + B_SZ;
    u32* sBih = dsm + 4 * A_SZ + 2 * B_SZ;
    u32* sBil = dsm + 4 * A_SZ + 3 * B_SZ;

    const int tid  = threadIdx.x;
    const int lane = tid & 31;
    const int wid  = tid >> 5;
    const int wm   = wid & 3;
    const int wn   = wid >> 2;
    const int g    = lane >> 2;
    const int tg   = lane & 3;

    const int m0 = blockIdx.y * 128;
    const int n0 = blockIdx.x * 64;

    const int arow = tid >> 1;
    const int aseg = (tid & 1) * 4;
    const int brow = tid >> 2;
    const int bseg = (tid & 3) * 2;

    float yr[2][4][4], yi[2][4][4];
#pragma unroll
    for (int mt = 0; mt < 2; mt++)
#pragma unroll
        for (int nt = 0; nt < 4; nt++)
#pragma unroll
            for (int c = 0; c < 4; c++) { yr[mt][nt][c] = 0.f; yi[mt][nt][c] = 0.f; }

    for (int k0 = 0; k0 < K; k0 += 32) {
        __syncthreads();
        {
            const float* pr = Xr + (size_t)(m0 + arow) * K + k0;
            const float* pi = Xi + (size_t)(m0 + arow) * K + k0;
#pragma unroll
            for (int s = 0; s < 4; s++) {
                int seg = aseg + s;
                float4 v = *(const float4*)(pr + seg * 4);
                u32 h0, l0, h1, l1;
                split_pack(v.x, v.y, h0, l0);
                split_pack(v.z, v.w, h1, l1);
                sArh[arow * APITCH + seg * 2]     = h0;
                sArh[arow * APITCH + seg * 2 + 1] = h1;
                sArl[arow * APITCH + seg * 2]     = l0;
                sArl[arow * APITCH + seg * 2 + 1] = l1;
                v = *(const float4*)(pi + seg * 4);
                split_pack(v.x, v.y, h0, l0);
                split_pack(v.z, v.w, h1, l1);
                sAih[arow * APITCH + seg * 2]     = h0;
                sAih[arow * APITCH + seg * 2 + 1] = h1;
                sAil[arow * APITCH + seg * 2]     = l0;
                sAil[arow * APITCH + seg * 2 + 1] = l1;
            }
        }
        {
            const float* pr = Wr + (size_t)(n0 + brow) * K + k0;
            const float* pi = Wi + (size_t)(n0 + brow) * K + k0;
#pragma unroll
            for (int s = 0; s < 2; s++) {
                int seg = bseg + s;
                float4 v = *(const float4*)(pr + seg * 4);
                u32 h0, l0, h1, l1;
                split_pack(v.x, v.y, h0, l0);
                split_pack(v.z, v.w, h1, l1);
                sBrh[brow * APITCH + seg * 2]     = h0;
                sBrh[brow * APITCH + seg * 2 + 1] = h1;
                sBrl[brow * APITCH + seg * 2]     = l0;
                sBrl[brow * APITCH + seg * 2 + 1] = l1;
                v = *(const float4*)(pi + seg * 4);
                split_pack(v.x, v.y, h0, l0);
                split_pack(v.z, v.w, h1, l1);
                sBih[brow * APITCH + seg * 2]     = h0;
                sBih[brow * APITCH + seg * 2 + 1] = h1;
                sBil[brow * APITCH + seg * 2]     = l0;
                sBil[brow * APITCH + seg * 2 + 1] = l1;
            }
        }
        __syncthreads();

#pragma unroll
        for (int ks = 0; ks < 2; ks++) {
            const int cb = ks * 8;
            u32 fArh[2][4], fArl[2][4], fAih[2][4], fAil[2][4];
#pragma unroll
            for (int mt = 0; mt < 2; mt++) {
                int r0 = wm * 32 + mt * 16 + g;
                int i00 = r0 * APITCH + cb + tg;
                int i08 = (r0 + 8) * APITCH + cb + tg;
                fArh[mt][0] = sArh[i00]; fArh[mt][1] = sArh[i08];
                fArh[mt][2] = sArh[i00 + 4]; fArh[mt][3] = sArh[i08 + 4];
                fArl[mt][0] = sArl[i00]; fArl[mt][1] = sArl[i08];
                fArl[mt][2] = sArl[i00 + 4]; fArl[mt][3] = sArl[i08 + 4];
                fAih[mt][0] = sAih[i00]; fAih[mt][1] = sAih[i08];
                fAih[mt][2] = sAih[i00 + 4]; fAih[mt][3] = sAih[i08 + 4];
                fAil[mt][0] = sAil[i00]; fAil[mt][1] = sAil[i08];
                fAil[mt][2] = sAil[i00 + 4]; fAil[mt][3] = sAil[i08 + 4];
            }
#pragma unroll
            for (int nt = 0; nt < 4; nt++) {
                int cn = wn * 32 + nt * 8 + g;
                int j0 = cn * APITCH + cb + tg;
                u32 fBrh[2] = { sBrh[j0], sBrh[j0 + 4] };
                u32 fBrl[2] = { sBrl[j0], sBrl[j0 + 4] };
                u32 fBih[2] = { sBih[j0], sBih[j0 + 4] };
                u32 fBil[2] = { sBil[j0], sBil[j0 + 4] };
                u32 fBihN[2] = { negbf2(fBih[0]), negbf2(fBih[1]) };
                u32 fBilN[2] = { negbf2(fBil[0]), negbf2(fBil[1]) };
#pragma unroll
                for (int mt = 0; mt < 2; mt++) {
                    mma16816(yr[mt][nt], fArh[mt], fBrh);
                    mma16816(yr[mt][nt], fArl[mt], fBrh);
                    mma16816(yr[mt][nt], fArh[mt], fBrl);
                    mma16816(yr[mt][nt], fAih[mt], fBihN);
                    mma16816(yr[mt][nt], fAil[mt], fBihN);
                    mma16816(yr[mt][nt], fAih[mt], fBilN);
                    mma16816(yi[mt][nt], fArh[mt], fBih);
                    mma16816(yi[mt][nt], fArl[mt], fBih);
                    mma16816(yi[mt][nt], fArh[mt], fBil);
                    mma16816(yi[mt][nt], fAih[mt], fBrh);
                    mma16816(yi[mt][nt], fAil[mt], fBrh);
                    mma16816(yi[mt][nt], fAih[mt], fBrl);
                }
            }
        }
    }

#pragma unroll
    for (int mt = 0; mt < 2; mt++) {
#pragma unroll
        for (int nt = 0; nt < 4; nt++) {
            int row = m0 + wm * 32 + mt * 16 + g;
            int col = n0 + wn * 32 + nt * 8 + tg * 2;
            size_t i0 = ((size_t)row * N + col) * ES;
            size_t i1 = ((size_t)(row + 8) * N + col) * ES;
            Yr[i0]      = yr[mt][nt][0];
            Yr[i0 + ES] = yr[mt][nt][1];
            Yi[i0]      = yi[mt][nt][0];
            Yi[i0 + ES] = yi[mt][nt][1];
            Yr[i1]      = yr[mt][nt][2];
            Yr[i1 + ES] = yr[mt][nt][3];
            Yi[i1]      = yi[mt][nt][2];
            Yi[i1 + ES] = yi[mt][nt][3];
        }
    }
}

#define GEMM_SMEM ((4 * A_SZ + 4 * B_SZ) * 4)

__global__ __launch_bounds__(256, 1) void cgemm_ts_proj(
    const float* __restrict__ Xr, const float* __restrict__ Xi,
    const float* __restrict__ Wr, const float* __restrict__ Wi,
    int which)
{
    float* Yr = (which == 0) ? g_qr : (which == 1) ? g_kr : g_vr;
    float* Yi = (which == 0) ? g_qi : (which == 1) ? g_ki : g_vi;
    cgemm_ts_body<1>(Xr, Xi, Wr, Wi, Yr, Yi, HD_, R_);
}

__global__ __launch_bounds__(256, 1) void cgemm_ts_out(
    const float* __restrict__ Wr, const float* __restrict__ Wi,
    float* __restrict__ out)
{
    cgemm_ts_body<2>(g_or, g_oi, Wr, Wi, out, out + 1, R_, HD_);
}

// ---------------------------------------------------------------------------
// Tensor-core complex-magnitude flash attention (split-bf16 mma.sync).
// Block = one (b,h) x 64 q rows; 8 warps: wm = wid&3 (16-row q block),
// wn = wid>>2 (32-col block of kv or d). 32 k-tiles of 64.
// Smem planes (u32 pitch 33): Q[4], K[4], V^T[4]; P(hi,lo) aliases K(rh,rl).
// ---------------------------------------------------------------------------
#define PITCH  33
#define PLANE  (64 * PITCH)
#define ATTN_SMEM ((12 * PLANE + 256) * 4)

__global__ __launch_bounds__(256, 2) void cattn_mma_kernel()
{
    extern __shared__ u32 dsm[];
    u32* sQrh = dsm;
    u32* sQrl = dsm + PLANE;
    u32* sQih = dsm + 2 * PLANE;
    u32* sQil = dsm + 3 * PLANE;
    u32* sKrh = dsm + 4 * PLANE;
    u32* sKrl = dsm + 5 * PLANE;
    u32* sKih = dsm + 6 * PLANE;
    u32* sKil = dsm + 7 * PLANE;
    u32* sVrh = dsm + 8 * PLANE;
    u32* sVrl = dsm + 9 * PLANE;
    u32* sVih = dsm + 10 * PLANE;
    u32* sVil = dsm + 11 * PLANE;
    float* redmax = (float*)(dsm + 12 * PLANE);   // [2][64]
    float* redsum = redmax + 128;                 // [2][64]
    u32* sPh = sKrh;   // alias: safe, K(rh/rl) consumed before P written
    u32* sPl = sKrl;

    const int tid  = threadIdx.x;
    const int lane = tid & 31;
    const int wid  = tid >> 5;
    const int wm   = wid & 3;
    const int wn   = wid >> 2;
    const int g    = lane >> 2;
    const int tg   = lane & 3;

    const int q0 = blockIdx.x * 64;
    const int bh = blockIdx.y;
    const int b  = bh >> 3, h = bh & 7;
    const int col0 = h * D_;

    const int srow = tid >> 2;          // staging row 0..63
    const int sseg = tid & 3;           // 16-float segment

    // --- stage Q once (split pairs, row-major over d) ---
    {
        const float* qr = g_qr + (size_t)(b * NQ_ + q0 + srow) * HD_ + col0 + sseg * 16;
        const float* qi = g_qi + (size_t)(b * NQ_ + q0 + srow) * HD_ + col0 + sseg * 16;
#pragma unroll
        for (int f = 0; f < 4; f++) {
            float4 v = *(const float4*)(qr + f * 4);
            u32 h0, l0, h1, l1;
            split_pack(v.x, v.y, h0, l0);
            split_pack(v.z, v.w, h1, l1);
            int o = srow * PITCH + sseg * 8 + f * 2;
            sQrh[o] = h0; sQrh[o + 1] = h1;
            sQrl[o] = l0; sQrl[o + 1] = l1;
            v = *(const float4*)(qi + f * 4);
            split_pack(v.x, v.y, h0, l0);
            split_pack(v.z, v.w, h1, l1);
            sQih[o] = h0; sQih[o + 1] = h1;
            sQil[o] = l0; sQil[o + 1] = l1;
        }
    }

    const int row0 = wm * 16 + g;
    const int row1 = row0 + 8;

    float mi0 = -CUDART_INF_F, mi1 = -CUDART_INF_F;
    float li0 = 0.f, li1 = 0.f;
    float o_re[4][4], o_im[4][4];
#pragma unroll
    for (int nt = 0; nt < 4; nt++)
#pragma unroll
        for (int c = 0; c < 4; c++) { o_re[nt][c] = 0.f; o_im[nt][c] = 0.f; }

    for (int kt = 0; kt < NK_ / 64; kt++) {
        const int n0 = kt * 64;
        __syncthreads();   // prior iteration's P/V reads done; Q visible (1st iter)

        // --- stage K (split pairs) and V^T (scalar split, d-major) ---
        {
            const float* kr = g_kr + (size_t)(b * NK_ + n0 + srow) * HD_ + col0 + sseg * 16;
            const float* ki = g_ki + (size_t)(b * NK_ + n0 + srow) * HD_ + col0 + sseg * 16;
#pragma unroll
            for (int f = 0; f < 4; f++) {
                float4 v = *(const float4*)(kr + f * 4);
                u32 h0, l0, h1, l1;
                split_pack(v.x, v.y, h0, l0);
                split_pack(v.z, v.w, h1, l1);
                int o = srow * PITCH + sseg * 8 + f * 2;
                sKrh[o] = h0; sKrh[o + 1] = h1;
                sKrl[o] = l0; sKrl[o + 1] = l1;
                v = *(const float4*)(ki + f * 4);
                split_pack(v.x, v.y, h0, l0);
                split_pack(v.z, v.w, h1, l1);
                sKih[o] = h0; sKih[o + 1] = h1;
                sKil[o] = l0; sKil[o + 1] = l1;
            }
            const float* vr = g_vr + (size_t)(b * NK_ + n0 + srow) * HD_ + col0 + sseg * 16;
            const float* vi = g_vi + (size_t)(b * NK_ + n0 + srow) * HD_ + col0 + sseg * 16;
            __nv_bfloat16* bVrh = (__nv_bfloat16*)sVrh;
            __nv_bfloat16* bVrl = (__nv_bfloat16*)sVrl;
            __nv_bfloat16* bVih = (__nv_bfloat16*)sVih;
            __nv_bfloat16* bVil = (__nv_bfloat16*)sVil;
#pragma unroll
            for (int f = 0; f < 4; f++) {
                float4 v = *(const float4*)(vr + f * 4);
                int d0 = sseg * 16 + f * 4;
                float xs[4] = {v.x, v.y, v.z, v.w};
#pragma unroll
                for (int e = 0; e < 4; e++) {
                    __nv_bfloat16 hh = __float2bfloat16(xs[e]);
                    bVrh[(d0 + e) * (2 * PITCH) + srow] = hh;
                    bVrl[(d0 + e) * (2 * PITCH) + srow] =
                        __float2bfloat16(xs[e] - __bfloat162float(hh));
                }
                v = *(const float4*)(vi + f * 4);
                float ys[4] = {v.x, v.y, v.z, v.w};
#pragma unroll
                for (int e = 0; e < 4; e++) {
                    __nv_bfloat16 hh = __float2bfloat16(ys[e]);
                    bVih[(d0 + e) * (2 * PITCH) + srow] = hh;
                    bVil[(d0 + e) * (2 * PITCH) + srow] =
                        __float2bfloat16(ys[e] - __bfloat162float(hh));
                }
            }
        }
        __syncthreads();

        // --- score MMAs: S(q x kv), A = Q, B = K ---
        float sre[4][4], sim[4][4];
#pragma unroll
        for (int nt = 0; nt < 4; nt++)
#pragma unroll
            for (int c = 0; c < 4; c++) { sre[nt][c] = 0.f; sim[nt][c] = 0.f; }

#pragma unroll
        for (int ks = 0; ks < 4; ks++) {
            const int cb = ks * 8;
            const int i00 = row0 * PITCH + cb + tg;
            const int i08 = row1 * PITCH + cb + tg;
            u32 fArh[4] = { sQrh[i00], sQrh[i08], sQrh[i00 + 4], sQrh[i08 + 4] };
            u32 fArl[4] = { sQrl[i00], sQrl[i08], sQrl[i00 + 4], sQrl[i08 + 4] };
            u32 fAih[4] = { sQih[i00], sQih[i08], sQih[i00 + 4], sQih[i08 + 4] };
            u32 fAil[4] = { sQil[i00], sQil[i08], sQil[i00 + 4], sQil[i08 + 4] };
#pragma unroll
            for (int nt = 0; nt < 4; nt++) {
                int cn = wn * 32 + nt * 8 + g;
                int j0 = cn * PITCH + cb + tg;
                u32 fBrh[2] = { sKrh[j0], sKrh[j0 + 4] };
                u32 fBrl[2] = { sKrl[j0], sKrl[j0 + 4] };
                u32 fBih[2] = { sKih[j0], sKih[j0 + 4] };
                u32 fBil[2] = { sKil[j0], sKil[j0 + 4] };
                u32 fBihN[2] = { negbf2(fBih[0]), negbf2(fBih[1]) };
                u32 fBilN[2] = { negbf2(fBil[0]), negbf2(fBil[1]) };
                // s_re = QrKr + QiKi
                mma16816(sre[nt], fArh, fBrh);
                mma16816(sre[nt], fArl, fBrh);
                mma16816(sre[nt], fArh, fBrl);
                mma16816(sre[nt], fAih, fBih);
                mma16816(sre[nt], fAil, fBih);
                mma16816(sre[nt], fAih, fBil);
                // s_im = QiKr - QrKi
                mma16816(sim[nt], fAih, fBrh);
                mma16816(sim[nt], fAil, fBrh);
                mma16816(sim[nt], fAih, fBrl);
                mma16816(sim[nt], fArh, fBihN);
                mma16816(sim[nt], fArl, fBihN);
                mma16816(sim[nt], fArh, fBilN);
            }
        }

        // --- magnitude + online softmax ---
        float p0[8], p1[8];
        float rm0 = -CUDART_INF_F, rm1 = -CUDART_INF_F;
#pragma unroll
        for (int nt = 0; nt < 4; nt++) {
#pragma unroll
            for (int c = 0; c < 2; c++) {
                float s2 = fmaf(sre[nt][c], sre[nt][c],
                                sim[nt][c] * sim[nt][c]) + 1e-30f;
                float mag = s2 * rsqrtf(s2) * 0.125f;
                p0[nt * 2 + c] = mag;
                rm0 = fmaxf(rm0, mag);
                float s2b = fmaf(sre[nt][c + 2], sre[nt][c + 2],
                                 sim[nt][c + 2] * sim[nt][c + 2]) + 1e-30f;
                float magb = s2b * rsqrtf(s2b) * 0.125f;
                p1[nt * 2 + c] = magb;
                rm1 = fmaxf(rm1, magb);
            }
        }
        rm0 = fmaxf(rm0, __shfl_xor_sync(0xffffffffu, rm0, 1));
        rm0 = fmaxf(rm0, __shfl_xor_sync(0xffffffffu, rm0, 2));
        rm1 = fmaxf(rm1, __shfl_xor_sync(0xffffffffu, rm1, 1));
        rm1 = fmaxf(rm1, __shfl_xor_sync(0xffffffffu, rm1, 2));
        if (tg == 0) {
            redmax[wn * 64 + row0] = rm0;
            redmax[wn * 64 + row1] = rm1;
        }
        __syncthreads();   // also fences K-plane reads before P overwrite

        float rowmax0 = fmaxf(redmax[row0], redmax[64 + row0]);
        float rowmax1 = fmaxf(redmax[row1], redmax[64 + row1]);
        float mnew0 = fmaxf(mi0, rowmax0);
        float mnew1 = fmaxf(mi1, rowmax1);
        float alpha0 = __expf(mi0 - mnew0);
        float alpha1 = __expf(mi1 - mnew1);
        mi0 = mnew0; mi1 = mnew1;

        float s0 = 0.f, s1 = 0.f;
#pragma unroll
        for (int j = 0; j < 8; j++) {
            p0[j] = __expf(p0[j] - mnew0); s0 += p0[j];
            p1[j] = __expf(p1[j] - mnew1); s1 += p1[j];
        }
        // write P (hi, lo) into aliased K planes, row-major pairs over kv
#pragma unroll
        for (int nt = 0; nt < 4; nt++) {
            u32 hh, ll;
            int o = row0 * PITCH + wn * 16 + nt * 4 + tg;
            split_pack(p0[nt * 2], p0[nt * 2 + 1], hh, ll);
            sPh[o] = hh; sPl[o] = ll;
            o = row1 * PITCH + wn * 16 + nt * 4 + tg;
            split_pack(p1[nt * 2], p1[nt * 2 + 1], hh, ll);
            sPh[o] = hh; sPl[o] = ll;
        }
        s0 += __shfl_xor_sync(0xffffffffu, s0, 1);
        s0 += __shfl_xor_sync(0xffffffffu, s0, 2);
        s1 += __shfl_xor_sync(0xffffffffu, s1, 1);
        s1 += __shfl_xor_sync(0xffffffffu, s1, 2);
        if (tg == 0) {
            redsum[wn * 64 + row0] = s0;
            redsum[wn * 64 + row1] = s1;
        }
        __syncthreads();   // P complete + sums visible

        li0 = li0 * alpha0 + redsum[row0] + redsum[64 + row0];
        li1 = li1 * alpha1 + redsum[row1] + redsum[64 + row1];
#pragma unroll
        for (int nt = 0; nt < 4; nt++) {
            o_re[nt][0] *= alpha0; o_re[nt][1] *= alpha0;
            o_re[nt][2] *= alpha1; o_re[nt][3] *= alpha1;
            o_im[nt][0] *= alpha0; o_im[nt][1] *= alpha0;
            o_im[nt][2] *= alpha1; o_im[nt][3] *= alpha1;
        }

        // --- O += P @ V : A = P (q x kv), B = V^T (d x kv) ---
#pragma unroll
        for (int ks = 0; ks < 4; ks++) {
            const int cb = ks * 8;
            const int i00 = row0 * PITCH + cb + tg;
            const int i08 = row1 * PITCH + cb + tg;
            u32 fPh[4] = { sPh[i00], sPh[i08], sPh[i00 + 4], sPh[i08 + 4] };
            u32 fPl[4] = { sPl[i00], sPl[i08], sPl[i00 + 4], sPl[i08 + 4] };
#pragma unroll
            for (int nt = 0; nt < 4; nt++) {
                int cn = wn * 32 + nt * 8 + g;
                int j0 = cn * PITCH + cb + tg;
                u32 fVrh[2] = { sVrh[j0], sVrh[j0 + 4] };
                u32 fVrl[2] = { sVrl[j0], sVrl[j0 + 4] };
                u32 fVih[2] = { sVih[j0], sVih[j0 + 4] };
                u32 fVil[2] = { sVil[j0], sVil[j0 + 4] };
                mma16816(o_re[nt], fPh, fVrh);
                mma16816(o_re[nt], fPl, fVrh);
                mma16816(o_re[nt], fPh, fVrl);
                mma16816(o_im[nt], fPh, fVih);
                mma16816(o_im[nt], fPl, fVih);
                mma16816(o_im[nt], fPh, fVil);
            }
        }
    }

    // --- epilogue: O / l -> merged-head layout ---
    float inv0 = 1.0f / li0;
    float inv1 = 1.0f / li1;
#pragma unroll
    for (int nt = 0; nt < 4; nt++) {
        int col = col0 + wn * 32 + nt * 8 + tg * 2;
        size_t b0 = (size_t)(b * NQ_ + q0 + row0) * HD_ + col;
        size_t b1 = (size_t)(b * NQ_ + q0 + row1) * HD_ + col;
        *(float2*)&g_or[b0] = make_float2(o_re[nt][0] * inv0, o_re[nt][1] * inv0);
        *(float2*)&g_or[b1] = make_float2(o_re[nt][2] * inv1, o_re[nt][3] * inv1);
        *(float2*)&g_oi[b0] = make_float2(o_im[nt][0] * inv0, o_im[nt][1] * inv0);
        *(float2*)&g_oi[b1] = make_float2(o_im[nt][2] * inv1, o_im[nt][3] * inv1);
    }
}

// ---------------------------------------------------------------------------
// Launch
// ---------------------------------------------------------------------------
extern "C" void kernel_launch(void* const* d_in, const int* in_sizes, int n_in,
                              void* d_out, int out_size)
{
    const float* Qr   = (const float*)d_in[0];
    const float* Qi   = (const float*)d_in[1];
    const float* Kr   = (const float*)d_in[2];
    const float* Ki   = (const float*)d_in[3];
    const float* Vr   = (const float*)d_in[4];
    const float* Vi   = (const float*)d_in[5];
    const float* wq_r = (const float*)d_in[6];
    const float* wq_i = (const float*)d_in[7];
    const float* wk_r = (const float*)d_in[8];
    const float* wk_i = (const float*)d_in[9];
    const float* wv_r = (const float*)d_in[10];
    const float* wv_i = (const float*)d_in[11];
    const float* wo_r = (const float*)d_in[12];
    const float* wo_i = (const float*)d_in[13];
    float* out = (float*)d_out;

    cudaFuncSetAttribute(cattn_mma_kernel,
                         cudaFuncAttributeMaxDynamicSharedMemorySize, ATTN_SMEM);
    cudaFuncSetAttribute(cgemm_ts_proj,
                         cudaFuncAttributeMaxDynamicSharedMemorySize, GEMM_SMEM);
    cudaFuncSetAttribute(cgemm_ts_out,
                         cudaFuncAttributeMaxDynamicSharedMemorySize, GEMM_SMEM);

    dim3 gb(HD_ / 64, M_ / 128);   // (8, 32)
    dim3 tb(256);

    // Input projections (complex, tensor cores): Q, K, V -> scratch
    cgemm_ts_proj<<<gb, tb, GEMM_SMEM>>>(Qr, Qi, wq_r, wq_i, 0);
    cgemm_ts_proj<<<gb, tb, GEMM_SMEM>>>(Kr, Ki, wk_r, wk_i, 1);
    cgemm_ts_proj<<<gb, tb, GEMM_SMEM>>>(Vr, Vi, wv_r, wv_i, 2);

    // Tensor-core complex-magnitude flash attention
    cattn_mma_kernel<<<dim3(NQ_ / 64, B_ * H_), tb, ATTN_SMEM>>>();

    // Output projection (complex, tensor cores), interleaved (B, NQ, R, 2)
    cgemm_ts_out<<<dim3(R_ / 64, M_ / 128), tb, GEMM_SMEM>>>(wo_r, wo_i, out);
}

// round 9
// speedup vs baseline: 2.0284x; 1.4209x over previous
#include <cuda_runtime.h>
#include <cuda_bf16.h>
#include <math_constants.h>

// Problem constants
#define B_   2
#define NQ_  2048
#define NK_  2048
#define R_   512
#define H_   8
#define D_   64
#define HD_  512
#define M_   (B_ * NQ_)   // 4096 rows for all projection GEMMs

typedef unsigned int       u32;
typedef unsigned long long u64;

// ---------------------------------------------------------------------------
// Scratch (device globals; no allocations allowed)
// ---------------------------------------------------------------------------
__device__ float g_qr[M_ * HD_];
__device__ float g_qi[M_ * HD_];
__device__ float g_kr[M_ * HD_];
__device__ float g_ki[M_ * HD_];
__device__ float g_vr[M_ * HD_];
__device__ float g_vi[M_ * HD_];
__device__ float g_or[M_ * HD_];
__device__ float g_oi[M_ * HD_];

// ---------------------------------------------------------------------------
// bf16 split helpers: x = hi + lo (each bf16), packed as bf16x2 in u32.
// ---------------------------------------------------------------------------
__device__ __forceinline__ void split_pack(float x0, float x1, u32& h, u32& l) {
    __nv_bfloat162 hv = __floats2bfloat162_rn(x0, x1);
    float h0 = __bfloat162float(__low2bfloat16(hv));
    float h1 = __bfloat162float(__high2bfloat16(hv));
    __nv_bfloat162 lv = __floats2bfloat162_rn(x0 - h0, x1 - h1);
    h = *reinterpret_cast<u32*>(&hv);
    l = *reinterpret_cast<u32*>(&lv);
}
__device__ __forceinline__ u32 negbf2(u32 x) { return x ^ 0x80008000u; }
__device__ __forceinline__ u64 mk64(u32 lo, u32 hi) {
    return (u64)lo | ((u64)hi << 32);
}

// mma.sync m16n8k16 row.col f32 += bf16 * bf16
__device__ __forceinline__ void mma16816(float* c, const u32* a, const u32* b) {
    asm volatile(
        "mma.sync.aligned.m16n8k16.row.col.f32.bf16.bf16.f32 "
        "{%0,%1,%2,%3}, {%4,%5,%6,%7}, {%8,%9}, {%0,%1,%2,%3};"
        : "+f"(c[0]), "+f"(c[1]), "+f"(c[2]), "+f"(c[3])
        : "r"(a[0]), "r"(a[1]), "r"(a[2]), "r"(a[3]), "r"(b[0]), "r"(b[1]));
}

// ldmatrix x2 transposed (for B fragments from row-major storage)
__device__ __forceinline__ void ldsm2t(u32* r, u32 saddr) {
    asm volatile(
        "ldmatrix.sync.aligned.m8n8.x2.trans.shared.b16 {%0,%1}, [%2];"
        : "=r"(r[0]), "=r"(r[1]) : "r"(saddr));
}

// ---------------------------------------------------------------------------
// Tensor-core complex GEMM with bf16 2-term split precision (validated R5).
// ---------------------------------------------------------------------------
#define APITCH 17            // u32 pitch for 16 k-pairs + 1 pad
#define A_SZ   (128 * APITCH)
#define B_SZ   (64  * APITCH)

template <int ES>
__device__ __forceinline__ void cgemm_ts_body(
    const float* __restrict__ Xr, const float* __restrict__ Xi,
    const float* __restrict__ Wr, const float* __restrict__ Wi,
    float* __restrict__ Yr, float* __restrict__ Yi,
    int N, int K)
{
    extern __shared__ u32 dsm[];
    u32* sArh = dsm;
    u32* sArl = dsm + A_SZ;
    u32* sAih = dsm + 2 * A_SZ;
    u32* sAil = dsm + 3 * A_SZ;
    u32* sBrh = dsm + 4 * A_SZ;
    u32* sBrl = dsm + 4 * A_SZ + B_SZ;
    u32* sBih = dsm + 4 * A_SZ + 2 * B_SZ;
    u32* sBil = dsm + 4 * A_SZ + 3 * B_SZ;

    const int tid  = threadIdx.x;
    const int lane = tid & 31;
    const int wid  = tid >> 5;
    const int wm   = wid & 3;
    const int wn   = wid >> 2;
    const int g    = lane >> 2;
    const int tg   = lane & 3;

    const int m0 = blockIdx.y * 128;
    const int n0 = blockIdx.x * 64;

    const int arow = tid >> 1;
    const int aseg = (tid & 1) * 4;
    const int brow = tid >> 2;
    const int bseg = (tid & 3) * 2;

    float yr[2][4][4], yi[2][4][4];
#pragma unroll
    for (int mt = 0; mt < 2; mt++)
#pragma unroll
        for (int nt = 0; nt < 4; nt++)
#pragma unroll
            for (int c = 0; c < 4; c++) { yr[mt][nt][c] = 0.f; yi[mt][nt][c] = 0.f; }

    for (int k0 = 0; k0 < K; k0 += 32) {
        __syncthreads();
        {
            const float* pr = Xr + (size_t)(m0 + arow) * K + k0;
            const float* pi = Xi + (size_t)(m0 + arow) * K + k0;
#pragma unroll
            for (int s = 0; s < 4; s++) {
                int seg = aseg + s;
                float4 v = *(const float4*)(pr + seg * 4);
                u32 h0, l0, h1, l1;
                split_pack(v.x, v.y, h0, l0);
                split_pack(v.z, v.w, h1, l1);
                sArh[arow * APITCH + seg * 2]     = h0;
                sArh[arow * APITCH + seg * 2 + 1] = h1;
                sArl[arow * APITCH + seg * 2]     = l0;
                sArl[arow * APITCH + seg * 2 + 1] = l1;
                v = *(const float4*)(pi + seg * 4);
                split_pack(v.x, v.y, h0, l0);
                split_pack(v.z, v.w, h1, l1);
                sAih[arow * APITCH + seg * 2]     = h0;
                sAih[arow * APITCH + seg * 2 + 1] = h1;
                sAil[arow * APITCH + seg * 2]     = l0;
                sAil[arow * APITCH + seg * 2 + 1] = l1;
            }
        }
        {
            const float* pr = Wr + (size_t)(n0 + brow) * K + k0;
            const float* pi = Wi + (size_t)(n0 + brow) * K + k0;
#pragma unroll
            for (int s = 0; s < 2; s++) {
                int seg = bseg + s;
                float4 v = *(const float4*)(pr + seg * 4);
                u32 h0, l0, h1, l1;
                split_pack(v.x, v.y, h0, l0);
                split_pack(v.z, v.w, h1, l1);
                sBrh[brow * APITCH + seg * 2]     = h0;
                sBrh[brow * APITCH + seg * 2 + 1] = h1;
                sBrl[brow * APITCH + seg * 2]     = l0;
                sBrl[brow * APITCH + seg * 2 + 1] = l1;
                v = *(const float4*)(pi + seg * 4);
                split_pack(v.x, v.y, h0, l0);
                split_pack(v.z, v.w, h1, l1);
                sBih[brow * APITCH + seg * 2]     = h0;
                sBih[brow * APITCH + seg * 2 + 1] = h1;
                sBil[brow * APITCH + seg * 2]     = l0;
                sBil[brow * APITCH + seg * 2 + 1] = l1;
            }
        }
        __syncthreads();

#pragma unroll
        for (int ks = 0; ks < 2; ks++) {
            const int cb = ks * 8;
            u32 fArh[2][4], fArl[2][4], fAih[2][4], fAil[2][4];
#pragma unroll
            for (int mt = 0; mt < 2; mt++) {
                int r0 = wm * 32 + mt * 16 + g;
                int i00 = r0 * APITCH + cb + tg;
                int i08 = (r0 + 8) * APITCH + cb + tg;
                fArh[mt][0] = sArh[i00]; fArh[mt][1] = sArh[i08];
                fArh[mt][2] = sArh[i00 + 4]; fArh[mt][3] = sArh[i08 + 4];
                fArl[mt][0] = sArl[i00]; fArl[mt][1] = sArl[i08];
                fArl[mt][2] = sArl[i00 + 4]; fArl[mt][3] = sArl[i08 + 4];
                fAih[mt][0] = sAih[i00]; fAih[mt][1] = sAih[i08];
                fAih[mt][2] = sAih[i00 + 4]; fAih[mt][3] = sAih[i08 + 4];
                fAil[mt][0] = sAil[i00]; fAil[mt][1] = sAil[i08];
                fAil[mt][2] = sAil[i00 + 4]; fAil[mt][3] = sAil[i08 + 4];
            }
#pragma unroll
            for (int nt = 0; nt < 4; nt++) {
                int cn = wn * 32 + nt * 8 + g;
                int j0 = cn * APITCH + cb + tg;
                u32 fBrh[2] = { sBrh[j0], sBrh[j0 + 4] };
                u32 fBrl[2] = { sBrl[j0], sBrl[j0 + 4] };
                u32 fBih[2] = { sBih[j0], sBih[j0 + 4] };
                u32 fBil[2] = { sBil[j0], sBil[j0 + 4] };
                u32 fBihN[2] = { negbf2(fBih[0]), negbf2(fBih[1]) };
                u32 fBilN[2] = { negbf2(fBil[0]), negbf2(fBil[1]) };
#pragma unroll
                for (int mt = 0; mt < 2; mt++) {
                    mma16816(yr[mt][nt], fArh[mt], fBrh);
                    mma16816(yr[mt][nt], fArl[mt], fBrh);
                    mma16816(yr[mt][nt], fArh[mt], fBrl);
                    mma16816(yr[mt][nt], fAih[mt], fBihN);
                    mma16816(yr[mt][nt], fAil[mt], fBihN);
                    mma16816(yr[mt][nt], fAih[mt], fBilN);
                    mma16816(yi[mt][nt], fArh[mt], fBih);
                    mma16816(yi[mt][nt], fArl[mt], fBih);
                    mma16816(yi[mt][nt], fArh[mt], fBil);
                    mma16816(yi[mt][nt], fAih[mt], fBrh);
                    mma16816(yi[mt][nt], fAil[mt], fBrh);
                    mma16816(yi[mt][nt], fAih[mt], fBrl);
                }
            }
        }
    }

#pragma unroll
    for (int mt = 0; mt < 2; mt++) {
#pragma unroll
        for (int nt = 0; nt < 4; nt++) {
            int row = m0 + wm * 32 + mt * 16 + g;
            int col = n0 + wn * 32 + nt * 8 + tg * 2;
            size_t i0 = ((size_t)row * N + col) * ES;
            size_t i1 = ((size_t)(row + 8) * N + col) * ES;
            Yr[i0]      = yr[mt][nt][0];
            Yr[i0 + ES] = yr[mt][nt][1];
            Yi[i0]      = yi[mt][nt][0];
            Yi[i0 + ES] = yi[mt][nt][1];
            Yr[i1]      = yr[mt][nt][2];
            Yr[i1 + ES] = yr[mt][nt][3];
            Yi[i1]      = yi[mt][nt][2];
            Yi[i1 + ES] = yi[mt][nt][3];
        }
    }
}

#define GEMM_SMEM ((4 * A_SZ + 4 * B_SZ) * 4)

__global__ __launch_bounds__(256, 1) void cgemm_ts_proj(
    const float* __restrict__ Xr, const float* __restrict__ Xi,
    const float* __restrict__ Wr, const float* __restrict__ Wi,
    int which)
{
    float* Yr = (which == 0) ? g_qr : (which == 1) ? g_kr : g_vr;
    float* Yi = (which == 0) ? g_qi : (which == 1) ? g_ki : g_vi;
    cgemm_ts_body<1>(Xr, Xi, Wr, Wi, Yr, Yi, HD_, R_);
}

__global__ __launch_bounds__(256, 1) void cgemm_ts_out(
    const float* __restrict__ Wr, const float* __restrict__ Wi,
    float* __restrict__ out)
{
    cgemm_ts_body<2>(g_or, g_oi, Wr, Wi, out, out + 1, R_, HD_);
}

// ---------------------------------------------------------------------------
// Tensor-core complex-magnitude flash attention (split-bf16 mma.sync).
// V stored row-major like K; PV B-fragments come via ldmatrix.x2.trans.
// PITCH = 36 u32 (144 B = 9x16) for ldmatrix row alignment; conflict-free.
// ---------------------------------------------------------------------------
#define PITCH  36
#define PLANE  (64 * PITCH)
#define ATTN_SMEM ((12 * PLANE + 256) * 4)

__global__ __launch_bounds__(256, 2) void cattn_mma_kernel()
{
    extern __shared__ u32 dsm[];
    u32* sQrh = dsm;
    u32* sQrl = dsm + PLANE;
    u32* sQih = dsm + 2 * PLANE;
    u32* sQil = dsm + 3 * PLANE;
    u32* sKrh = dsm + 4 * PLANE;
    u32* sKrl = dsm + 5 * PLANE;
    u32* sKih = dsm + 6 * PLANE;
    u32* sKil = dsm + 7 * PLANE;
    u32* sVrh = dsm + 8 * PLANE;
    u32* sVrl = dsm + 9 * PLANE;
    u32* sVih = dsm + 10 * PLANE;
    u32* sVil = dsm + 11 * PLANE;
    float* redmax = (float*)(dsm + 12 * PLANE);   // [2][64]
    float* redsum = redmax + 128;                 // [2][64]
    u32* sPh = sKrh;   // alias: K(rh/rl) consumed before P written
    u32* sPl = sKrl;

    const int tid  = threadIdx.x;
    const int lane = tid & 31;
    const int wid  = tid >> 5;
    const int wm   = wid & 3;
    const int wn   = wid >> 2;
    const int g    = lane >> 2;
    const int tg   = lane & 3;

    const int q0 = blockIdx.x * 64;
    const int bh = blockIdx.y;
    const int b  = bh >> 3, h = bh & 7;
    const int col0 = h * D_;

    const int srow = tid >> 2;          // staging row 0..63
    const int sseg = tid & 3;           // 16-float segment

    // ldmatrix.trans lane row pattern for V B-fragments (x2)
    const int vlrow = (lane & 7) + ((lane >> 3) & 1) * 8;

    // --- stage Q once (split pairs, row-major over d) ---
    {
        const float* qr = g_qr + (size_t)(b * NQ_ + q0 + srow) * HD_ + col0 + sseg * 16;
        const float* qi = g_qi + (size_t)(b * NQ_ + q0 + srow) * HD_ + col0 + sseg * 16;
#pragma unroll
        for (int f = 0; f < 4; f++) {
            float4 v = *(const float4*)(qr + f * 4);
            u32 h0, l0, h1, l1;
            split_pack(v.x, v.y, h0, l0);
            split_pack(v.z, v.w, h1, l1);
            int o = srow * PITCH + sseg * 8 + f * 2;
            *(u64*)&sQrh[o] = mk64(h0, h1);
            *(u64*)&sQrl[o] = mk64(l0, l1);
            v = *(const float4*)(qi + f * 4);
            split_pack(v.x, v.y, h0, l0);
            split_pack(v.z, v.w, h1, l1);
            *(u64*)&sQih[o] = mk64(h0, h1);
            *(u64*)&sQil[o] = mk64(l0, l1);
        }
    }

    const int row0 = wm * 16 + g;
    const int row1 = row0 + 8;

    float mi0 = -CUDART_INF_F, mi1 = -CUDART_INF_F;
    float li0 = 0.f, li1 = 0.f;
    float o_re[4][4], o_im[4][4];
#pragma unroll
    for (int nt = 0; nt < 4; nt++)
#pragma unroll
        for (int c = 0; c < 4; c++) { o_re[nt][c] = 0.f; o_im[nt][c] = 0.f; }

    for (int kt = 0; kt < NK_ / 64; kt++) {
        const int n0 = kt * 64;
        __syncthreads();   // prior iteration's P/V reads done

        // --- stage K and V (both row-major split planes, u64 stores) ---
        {
            const size_t rb = (size_t)(b * NK_ + n0 + srow) * HD_ + col0 + sseg * 16;
            const float* kr = g_kr + rb;
            const float* ki = g_ki + rb;
            const float* vr = g_vr + rb;
            const float* vi = g_vi + rb;
#pragma unroll
            for (int f = 0; f < 4; f++) {
                int o = srow * PITCH + sseg * 8 + f * 2;
                u32 h0, l0, h1, l1;
                float4 v = *(const float4*)(kr + f * 4);
                split_pack(v.x, v.y, h0, l0);
                split_pack(v.z, v.w, h1, l1);
                *(u64*)&sKrh[o] = mk64(h0, h1);
                *(u64*)&sKrl[o] = mk64(l0, l1);
                v = *(const float4*)(ki + f * 4);
                split_pack(v.x, v.y, h0, l0);
                split_pack(v.z, v.w, h1, l1);
                *(u64*)&sKih[o] = mk64(h0, h1);
                *(u64*)&sKil[o] = mk64(l0, l1);
                v = *(const float4*)(vr + f * 4);
                split_pack(v.x, v.y, h0, l0);
                split_pack(v.z, v.w, h1, l1);
                *(u64*)&sVrh[o] = mk64(h0, h1);
                *(u64*)&sVrl[o] = mk64(l0, l1);
                v = *(const float4*)(vi + f * 4);
                split_pack(v.x, v.y, h0, l0);
                split_pack(v.z, v.w, h1, l1);
                *(u64*)&sVih[o] = mk64(h0, h1);
                *(u64*)&sVil[o] = mk64(l0, l1);
            }
        }
        __syncthreads();

        // --- score MMAs: S(q x kv), A = Q, B = K ---
        float sre[4][4], sim[4][4];
#pragma unroll
        for (int nt = 0; nt < 4; nt++)
#pragma unroll
            for (int c = 0; c < 4; c++) { sre[nt][c] = 0.f; sim[nt][c] = 0.f; }

#pragma unroll
        for (int ks = 0; ks < 4; ks++) {
            const int cb = ks * 8;
            const int i00 = row0 * PITCH + cb + tg;
            const int i08 = row1 * PITCH + cb + tg;
            u32 fArh[4] = { sQrh[i00], sQrh[i08], sQrh[i00 + 4], sQrh[i08 + 4] };
            u32 fArl[4] = { sQrl[i00], sQrl[i08], sQrl[i00 + 4], sQrl[i08 + 4] };
            u32 fAih[4] = { sQih[i00], sQih[i08], sQih[i00 + 4], sQih[i08 + 4] };
            u32 fAil[4] = { sQil[i00], sQil[i08], sQil[i00 + 4], sQil[i08 + 4] };
#pragma unroll
            for (int nt = 0; nt < 4; nt++) {
                int cn = wn * 32 + nt * 8 + g;
                int j0 = cn * PITCH + cb + tg;
                u32 fBrh[2] = { sKrh[j0], sKrh[j0 + 4] };
                u32 fBrl[2] = { sKrl[j0], sKrl[j0 + 4] };
                u32 fBih[2] = { sKih[j0], sKih[j0 + 4] };
                u32 fBil[2] = { sKil[j0], sKil[j0 + 4] };
                u32 fBihN[2] = { negbf2(fBih[0]), negbf2(fBih[1]) };
                u32 fBilN[2] = { negbf2(fBil[0]), negbf2(fBil[1]) };
                // s_re = QrKr + QiKi
                mma16816(sre[nt], fArh, fBrh);
                mma16816(sre[nt], fArl, fBrh);
                mma16816(sre[nt], fArh, fBrl);
                mma16816(sre[nt], fAih, fBih);
                mma16816(sre[nt], fAil, fBih);
                mma16816(sre[nt], fAih, fBil);
                // s_im = QiKr - QrKi
                mma16816(sim[nt], fAih, fBrh);
                mma16816(sim[nt], fAil, fBrh);
                mma16816(sim[nt], fAih, fBrl);
                mma16816(sim[nt], fArh, fBihN);
                mma16816(sim[nt], fArl, fBihN);
                mma16816(sim[nt], fArh, fBilN);
            }
        }

        // --- magnitude + online softmax ---
        float p0[8], p1[8];
        float rm0 = -CUDART_INF_F, rm1 = -CUDART_INF_F;
#pragma unroll
        for (int nt = 0; nt < 4; nt++) {
#pragma unroll
            for (int c = 0; c < 2; c++) {
                float s2 = fmaf(sre[nt][c], sre[nt][c],
                                sim[nt][c] * sim[nt][c]) + 1e-30f;
                float mag = s2 * rsqrtf(s2) * 0.125f;
                p0[nt * 2 + c] = mag;
                rm0 = fmaxf(rm0, mag);
                float s2b = fmaf(sre[nt][c + 2], sre[nt][c + 2],
                                 sim[nt][c + 2] * sim[nt][c + 2]) + 1e-30f;
                float magb = s2b * rsqrtf(s2b) * 0.125f;
                p1[nt * 2 + c] = magb;
                rm1 = fmaxf(rm1, magb);
            }
        }
        rm0 = fmaxf(rm0, __shfl_xor_sync(0xffffffffu, rm0, 1));
        rm0 = fmaxf(rm0, __shfl_xor_sync(0xffffffffu, rm0, 2));
        rm1 = fmaxf(rm1, __shfl_xor_sync(0xffffffffu, rm1, 1));
        rm1 = fmaxf(rm1, __shfl_xor_sync(0xffffffffu, rm1, 2));
        if (tg == 0) {
            redmax[wn * 64 + row0] = rm0;
            redmax[wn * 64 + row1] = rm1;
        }
        __syncthreads();   // fences K-plane reads before P overwrite

        float rowmax0 = fmaxf(redmax[row0], redmax[64 + row0]);
        float rowmax1 = fmaxf(redmax[row1], redmax[64 + row1]);
        float mnew0 = fmaxf(mi0, rowmax0);
        float mnew1 = fmaxf(mi1, rowmax1);
        float alpha0 = __expf(mi0 - mnew0);
        float alpha1 = __expf(mi1 - mnew1);
        mi0 = mnew0; mi1 = mnew1;

        float s0 = 0.f, s1 = 0.f;
#pragma unroll
        for (int j = 0; j < 8; j++) {
            p0[j] = __expf(p0[j] - mnew0); s0 += p0[j];
            p1[j] = __expf(p1[j] - mnew1); s1 += p1[j];
        }
        // write P (hi, lo) into aliased K planes, row-major pairs over kv
#pragma unroll
        for (int nt = 0; nt < 4; nt++) {
            u32 hh, ll;
            int o = row0 * PITCH + wn * 16 + nt * 4 + tg;
            split_pack(p0[nt * 2], p0[nt * 2 + 1], hh, ll);
            sPh[o] = hh; sPl[o] = ll;
            o = row1 * PITCH + wn * 16 + nt * 4 + tg;
            split_pack(p1[nt * 2], p1[nt * 2 + 1], hh, ll);
            sPh[o] = hh; sPl[o] = ll;
        }
        s0 += __shfl_xor_sync(0xffffffffu, s0, 1);
        s0 += __shfl_xor_sync(0xffffffffu, s0, 2);
        s1 += __shfl_xor_sync(0xffffffffu, s1, 1);
        s1 += __shfl_xor_sync(0xffffffffu, s1, 2);
        if (tg == 0) {
            redsum[wn * 64 + row0] = s0;
            redsum[wn * 64 + row1] = s1;
        }
        __syncthreads();   // P complete + sums visible

        li0 = li0 * alpha0 + redsum[row0] + redsum[64 + row0];
        li1 = li1 * alpha1 + redsum[row1] + redsum[64 + row1];
#pragma unroll
        for (int nt = 0; nt < 4; nt++) {
            o_re[nt][0] *= alpha0; o_re[nt][1] *= alpha0;
            o_re[nt][2] *= alpha1; o_re[nt][3] *= alpha1;
            o_im[nt][0] *= alpha0; o_im[nt][1] *= alpha0;
            o_im[nt][2] *= alpha1; o_im[nt][3] *= alpha1;
        }

        // --- O += P @ V : A = P (q x kv), B = V row-major via ldmatrix.trans ---
#pragma unroll
        for (int ks = 0; ks < 4; ks++) {
            const int cb = ks * 8;
            const int i00 = row0 * PITCH + cb + tg;
            const int i08 = row1 * PITCH + cb + tg;
            u32 fPh[4] = { sPh[i00], sPh[i08], sPh[i00 + 4], sPh[i08 + 4] };
            u32 fPl[4] = { sPl[i00], sPl[i08], sPl[i00 + 4], sPl[i08 + 4] };
            // per-lane byte address base for V rows (kv = ks*16 + vlrow)
            const int vrow = ks * 16 + vlrow;
            u32 avrh = (u32)__cvta_generic_to_shared(sVrh + vrow * PITCH + wn * 16);
            u32 avrl = (u32)__cvta_generic_to_shared(sVrl + vrow * PITCH + wn * 16);
            u32 avih = (u32)__cvta_generic_to_shared(sVih + vrow * PITCH + wn * 16);
            u32 avil = (u32)__cvta_generic_to_shared(sVil + vrow * PITCH + wn * 16);
#pragma unroll
            for (int nt = 0; nt < 4; nt++) {
                u32 off = nt * 16;   // nt*4 u32 = 16 bytes
                u32 fVrh[2], fVrl[2], fVih[2], fVil[2];
                ldsm2t(fVrh, avrh + off);
                ldsm2t(fVrl, avrl + off);
                ldsm2t(fVih, avih + off);
                ldsm2t(fVil, avil + off);
                mma16816(o_re[nt], fPh, fVrh);
                mma16816(o_re[nt], fPl, fVrh);
                mma16816(o_re[nt], fPh, fVrl);
                mma16816(o_im[nt], fPh, fVih);
                mma16816(o_im[nt], fPl, fVih);
                mma16816(o_im[nt], fPh, fVil);
            }
        }
    }

    // --- epilogue: O / l -> merged-head layout ---
    float inv0 = 1.0f / li0;
    float inv1 = 1.0f / li1;
#pragma unroll
    for (int nt = 0; nt < 4; nt++) {
        int col = col0 + wn * 32 + nt * 8 + tg * 2;
        size_t b0 = (size_t)(b * NQ_ + q0 + row0) * HD_ + col;
        size_t b1 = (size_t)(b * NQ_ + q0 + row1) * HD_ + col;
        *(float2*)&g_or[b0] = make_float2(o_re[nt][0] * inv0, o_re[nt][1] * inv0);
        *(float2*)&g_or[b1] = make_float2(o_re[nt][2] * inv1, o_re[nt][3] * inv1);
        *(float2*)&g_oi[b0] = make_float2(o_im[nt][0] * inv0, o_im[nt][1] * inv0);
        *(float2*)&g_oi[b1] = make_float2(o_im[nt][2] * inv1, o_im[nt][3] * inv1);
    }
}

// ---------------------------------------------------------------------------
// Launch
// ---------------------------------------------------------------------------
extern "C" void kernel_launch(void* const* d_in, const int* in_sizes, int n_in,
                              void* d_out, int out_size)
{
    const float* Qr   = (const float*)d_in[0];
    const float* Qi   = (const float*)d_in[1];
    const float* Kr   = (const float*)d_in[2];
    const float* Ki   = (const float*)d_in[3];
    const float* Vr   = (const float*)d_in[4];
    const float* Vi   = (const float*)d_in[5];
    const float* wq_r = (const float*)d_in[6];
    const float* wq_i = (const float*)d_in[7];
    const float* wk_r = (const float*)d_in[8];
    const float* wk_i = (const float*)d_in[9];
    const float* wv_r = (const float*)d_in[10];
    const float* wv_i = (const float*)d_in[11];
    const float* wo_r = (const float*)d_in[12];
    const float* wo_i = (const float*)d_in[13];
    float* out = (float*)d_out;

    cudaFuncSetAttribute(cattn_mma_kernel,
                         cudaFuncAttributeMaxDynamicSharedMemorySize, ATTN_SMEM);
    cudaFuncSetAttribute(cgemm_ts_proj,
                         cudaFuncAttributeMaxDynamicSharedMemorySize, GEMM_SMEM);
    cudaFuncSetAttribute(cgemm_ts_out,
                         cudaFuncAttributeMaxDynamicSharedMemorySize, GEMM_SMEM);

    dim3 gb(HD_ / 64, M_ / 128);   // (8, 32)
    dim3 tb(256);

    // Input projections (complex, tensor cores): Q, K, V -> scratch
    cgemm_ts_proj<<<gb, tb, GEMM_SMEM>>>(Qr, Qi, wq_r, wq_i, 0);
    cgemm_ts_proj<<<gb, tb, GEMM_SMEM>>>(Kr, Ki, wk_r, wk_i, 1);
    cgemm_ts_proj<<<gb, tb, GEMM_SMEM>>>(Vr, Vi, wv_r, wv_i, 2);

    // Tensor-core complex-magnitude flash attention
    cattn_mma_kernel<<<dim3(NQ_ / 64, B_ * H_), tb, ATTN_SMEM>>>();

    // Output projection (complex, tensor cores), interleaved (B, NQ, R, 2)
    cgemm_ts_out<<<dim3(R_ / 64, M_ / 128), tb, GEMM_SMEM>>>(wo_r, wo_i, out);
}